// round 6
// baseline (speedup 1.0000x reference)
#include <cuda_runtime.h>
#include <cuda_fp16.h>
#include <cstdint>

#define NN 100000
#define EE 1600000
#define EPP 200000

// ---------------- scratch (static device globals; no allocation) ------------
__device__ int      g_deg[NN];
__device__ int      g_off[NN + 1];
__device__ int      g_cur[NN];
__device__ int      g_adj[EE];
__device__ float    g_dinv[NN];
__device__ __half   g_hs1[(size_t)NN * 128]; // x@W1 (unscaled, fp16)
__device__ __half   g_a1h[(size_t)NN * 128]; // aggregated layer-1 (fp16)
__device__ __half   g_hs2[(size_t)NN * 64];  // relu(a1+b1)@W2 (unscaled, fp16)
__device__ __half   g_z  [(size_t)NN * 64];  // final embeddings (fp16)
__device__ int      g_bsum[256];
__device__ int      g_boff[256];
// packed weights: [n][k2] half2 = (W[2k2][n], W[2k2+1][n]), hi and lo parts
__device__ unsigned g_W1ph[128 * 64], g_W1pl[128 * 64];
__device__ unsigned g_W2ph[64 * 64],  g_W2pl[64 * 64];

// ---------------- fp16 helpers ----------------------------------------------
__device__ __forceinline__ unsigned f2h2(float a, float b) {
    __half2 h = __floats2half2_rn(a, b);
    return *reinterpret_cast<unsigned*>(&h);
}
__device__ __forceinline__ float2 h2f2(unsigned u) {
    __half2 h = *reinterpret_cast<__half2*>(&u);
    return __half22float2(h);
}

__device__ __forceinline__ void mmaf16(float* c, const unsigned* a, unsigned b0, unsigned b1) {
    asm("mma.sync.aligned.m16n8k16.row.col.f32.f16.f16.f32 "
        "{%0,%1,%2,%3}, {%4,%5,%6,%7}, {%8,%9}, {%0,%1,%2,%3};"
        : "+f"(c[0]), "+f"(c[1]), "+f"(c[2]), "+f"(c[3])
        : "r"(a[0]), "r"(a[1]), "r"(a[2]), "r"(a[3]), "r"(b0), "r"(b1));
}

__device__ __forceinline__ void ldsm4(unsigned* r, unsigned addr) {
    asm volatile("ldmatrix.sync.aligned.m8n8.x4.shared.b16 {%0,%1,%2,%3}, [%4];"
        : "=r"(r[0]), "=r"(r[1]), "=r"(r[2]), "=r"(r[3]) : "r"(addr));
}

// ---------------- degree / CSR build ----------------------------------------
__global__ void k_init_deg() {
    int i = blockIdx.x * blockDim.x + threadIdx.x;
    if (i < NN) g_deg[i] = 0;
}

__global__ void k_count(const int* __restrict__ dst) {
    int e = blockIdx.x * blockDim.x + threadIdx.x;
    if (e < EE) atomicAdd(&g_deg[dst[e]], 1);
}

__global__ void k_dinv() {
    int i = blockIdx.x * blockDim.x + threadIdx.x;
    if (i < NN) g_dinv[i] = rsqrtf((float)(g_deg[i] + 1));  // +1 self loop
}

__global__ void k_scan1() {
    __shared__ int s[512];
    int t = threadIdx.x;
    int idx = blockIdx.x * 512 + t;
    int v = (idx < NN) ? g_deg[idx] : 0;
    s[t] = v;
    __syncthreads();
#pragma unroll
    for (int o = 1; o < 512; o <<= 1) {
        int x = (t >= o) ? s[t - o] : 0;
        __syncthreads();
        s[t] += x;
        __syncthreads();
    }
    if (idx < NN) g_off[idx] = s[t] - v;
    if (t == 511) g_bsum[blockIdx.x] = s[511];
}

__global__ void k_scan2(int nb) {
    __shared__ int s[256];
    int t = threadIdx.x;
    int v = (t < nb) ? g_bsum[t] : 0;
    s[t] = v;
    __syncthreads();
#pragma unroll
    for (int o = 1; o < 256; o <<= 1) {
        int x = (t >= o) ? s[t - o] : 0;
        __syncthreads();
        s[t] += x;
        __syncthreads();
    }
    if (t < nb) g_boff[t] = s[t] - v;
}

__global__ void k_scan3() {
    int t = threadIdx.x;
    int idx = blockIdx.x * 512 + t;
    if (idx < NN) {
        int val = g_off[idx] + g_boff[blockIdx.x];
        g_off[idx] = val;
        g_cur[idx] = val;
        if (idx == 0) g_off[NN] = EE;
    }
}

__global__ void k_fill(const int* __restrict__ src, const int* __restrict__ dst) {
    int e = blockIdx.x * blockDim.x + threadIdx.x;
    if (e < EE) {
        int d = dst[e];
        int p = atomicAdd(&g_cur[d], 1);
        g_adj[p] = src[e];
    }
}

// ---------------- weight hi/lo split + transpose-pack ------------------------
__global__ void k_wprep(const float* __restrict__ W1, const float* __restrict__ W2) {
    int i = blockIdx.x * blockDim.x + threadIdx.x;
    if (i < 128 * 64) {
        int n = i >> 6, k2 = i & 63;
        float w0 = W1[(2 * k2) * 128 + n];
        float w1 = W1[(2 * k2 + 1) * 128 + n];
        unsigned h = f2h2(w0, w1);
        float2 hf = h2f2(h);
        g_W1ph[i] = h;
        g_W1pl[i] = f2h2(w0 - hf.x, w1 - hf.y);
    } else if (i < 128 * 64 + 64 * 64) {
        int j = i - 128 * 64;
        int n = j >> 6, k2 = j & 63;
        float w0 = W2[(2 * k2) * 64 + n];
        float w1 = W2[(2 * k2 + 1) * 64 + n];
        unsigned h = f2h2(w0, w1);
        float2 hf = h2f2(h);
        g_W2ph[j] = h;
        g_W2pl[j] = f2h2(w0 - hf.x, w1 - hf.y);
    }
}

// ---------------- tensor-core GEMM, ldmatrix frags ---------------------------
// LAYER 1: hs1[NN,128] = x @ W1 (fp32 in, 3-term hi/lo split), MT=128, NOUT=128
// LAYER 2: hs2[NN,64] = relu(a1h+b1)@W2 (fp16 A exact, 2-term), MT=256, NOUT=64
// block = 256 threads = 8 warps; warp tile 32x64(L1) / 32x64(L2); K=128, 8 kc.
template<int LAYER>
__global__ __launch_bounds__(256) void k_tc(const float* __restrict__ Xsrc,
                                            const float* __restrict__ bias,
                                            int rowbase) {
    constexpr int MT   = (LAYER == 1) ? 128 : 256;
    constexpr int NOUT = (LAYER == 1) ? 128 : 64;

    const unsigned* Wph = (LAYER == 1) ? g_W1ph : g_W2ph;
    const unsigned* Wpl = (LAYER == 1) ? g_W1pl : g_W2pl;
    __half*         Out = (LAYER == 1) ? g_hs1 : g_hs2;

    __shared__ unsigned Ah[MT * 12];
    __shared__ unsigned Al[(LAYER == 1) ? MT * 12 : 12];   // unused for L2
    __shared__ unsigned Bh[NOUT * 12], Bl[NOUT * 12];

    const int tid  = threadIdx.x;
    const int lane = tid & 31;
    const int wid  = tid >> 5;
    const int g    = lane >> 2;
    const int t4   = lane & 3;
    const int row0 = rowbase + blockIdx.x * MT;
    const int warpM = (LAYER == 1) ? (wid >> 1) * 32 : wid * 32;
    const int n0    = (LAYER == 1) ? (wid & 1) * 64 : 0;

    // precomputed ldmatrix lane addresses (byte, shared space)
    const unsigned sAh = (unsigned)__cvta_generic_to_shared(Ah);
    const unsigned sAl = (unsigned)__cvta_generic_to_shared(Al);
    const unsigned sBh = (unsigned)__cvta_generic_to_shared(Bh);
    const unsigned sBl = (unsigned)__cvta_generic_to_shared(Bl);
    const int l7 = lane & 7;
    const int r8 = (lane >> 3) & 1;   // +8 rows for matrices 1,3 (A)
    const int w4 = (lane >> 4) * 4;   // word +4 for matrices 2,3 (A)
    unsigned aAddrOff[2];
#pragma unroll
    for (int mi = 0; mi < 2; mi++) {
        int row = warpM + mi * 16 + l7 + r8 * 8;
        aAddrOff[mi] = (unsigned)((row * 12 + w4) * 4);
    }
    unsigned bAddr[4], blAddr[4];
    const int bw4 = ((lane >> 3) & 1) * 4;        // word +4 for matrices 1,3 (B)
    const int bn8 = (lane >= 16) ? 8 : 0;         // +8 n-rows for matrices 2,3
#pragma unroll
    for (int nn = 0; nn < 4; nn++) {
        int nrow = n0 + nn * 16 + l7 + bn8;
        unsigned off = (unsigned)((nrow * 12 + bw4) * 4);
        bAddr[nn]  = sBh + off;
        blAddr[nn] = sBl + off;
    }

    float acc[2][8][4];
#pragma unroll
    for (int mi = 0; mi < 2; mi++)
#pragma unroll
        for (int ni = 0; ni < 8; ni++)
#pragma unroll
            for (int q = 0; q < 4; q++) acc[mi][ni][q] = 0.f;

#pragma unroll 1
    for (int kc = 0; kc < 8; kc++) {
        const int kbase = kc * 16;
        // ---- stage A chunk [MT x 16] ----------------------------------------
        if (LAYER == 1) {
#pragma unroll
            for (int j = 0; j < MT / 64; j++) {
                int idx = tid + 256 * j;
                int r = idx >> 2, c4 = idx & 3;
                int gr = row0 + r;
                float4 v = {0.f, 0.f, 0.f, 0.f};
                if (gr < NN)
                    v = ((const float4*)(Xsrc + (size_t)gr * 128 + kbase))[c4];
                unsigned h01 = f2h2(v.x, v.y), h23 = f2h2(v.z, v.w);
                float2 f01 = h2f2(h01), f23 = h2f2(h23);
                unsigned l01 = f2h2(v.x - f01.x, v.y - f01.y);
                unsigned l23 = f2h2(v.z - f23.x, v.w - f23.y);
                *(uint2*)&Ah[r * 12 + c4 * 2] = make_uint2(h01, h23);
                *(uint2*)&Al[r * 12 + c4 * 2] = make_uint2(l01, l23);
            }
        } else {
            // one thread per row: load 16 halfs, bias+relu, store 8 words
            int r = tid;
            int gr = row0 + r;
            uint4 u0 = {0,0,0,0}, u1 = {0,0,0,0};
            if (gr < NN) {
                const uint4* p = (const uint4*)(g_a1h + (size_t)gr * 128 + kbase);
                u0 = p[0]; u1 = p[1];
                const float2* bp = (const float2*)(bias + kbase);
                unsigned* uw = &u0.x;
#pragma unroll
                for (int w = 0; w < 4; w++) {
                    float2 f = h2f2(uw[w]); float2 b = bp[w];
                    uw[w] = f2h2(fmaxf(f.x + b.x, 0.f), fmaxf(f.y + b.y, 0.f));
                }
                unsigned* uw1 = &u1.x;
#pragma unroll
                for (int w = 0; w < 4; w++) {
                    float2 f = h2f2(uw1[w]); float2 b = bp[w + 4];
                    uw1[w] = f2h2(fmaxf(f.x + b.x, 0.f), fmaxf(f.y + b.y, 0.f));
                }
            }
            *(uint4*)&Ah[r * 12]     = u0;
            *(uint4*)&Ah[r * 12 + 4] = u1;
        }
        // ---- stage W chunk [NOUT x 8 half2] ---------------------------------
#pragma unroll
        for (int j = 0; j < NOUT / 64; j++) {
            int idx = tid + 256 * j;
            int n = idx >> 2, jp = (idx & 3) * 2;
            uint2 vh = *(const uint2*)&Wph[n * 64 + kc * 8 + jp];
            uint2 vl = *(const uint2*)&Wpl[n * 64 + kc * 8 + jp];
            *(uint2*)&Bh[n * 12 + jp] = vh;
            *(uint2*)&Bl[n * 12 + jp] = vl;
        }
        __syncthreads();

        // ---- fragments + mma ------------------------------------------------
        unsigned ah[2][4], al[2][4];
#pragma unroll
        for (int mi = 0; mi < 2; mi++) {
            ldsm4(ah[mi], sAh + aAddrOff[mi]);
            if (LAYER == 1) ldsm4(al[mi], sAl + aAddrOff[mi]);
        }
#pragma unroll
        for (int nn = 0; nn < 4; nn++) {
            unsigned bh[4], bl[4];
            ldsm4(bh, bAddr[nn]);
            ldsm4(bl, blAddr[nn]);
#pragma unroll
            for (int p = 0; p < 2; p++) {
                int ni = nn * 2 + p;
                unsigned b0 = bh[p * 2], b1 = bh[p * 2 + 1];
                unsigned c0 = bl[p * 2], c1 = bl[p * 2 + 1];
#pragma unroll
                for (int mi = 0; mi < 2; mi++) {
                    mmaf16(acc[mi][ni], ah[mi], b0, b1);            // hi*hi
                    if (LAYER == 1) mmaf16(acc[mi][ni], al[mi], b0, b1); // lo*hi
                    mmaf16(acc[mi][ni], ah[mi], c0, c1);            // hi*lo
                }
            }
        }
        __syncthreads();
    }

    // ---- epilogue: fp16 output (dinv applied in aggregation) ----------------
#pragma unroll
    for (int mi = 0; mi < 2; mi++) {
#pragma unroll
        for (int ni = 0; ni < 8; ni++) {
            int r  = row0 + warpM + mi * 16 + g;
            int cc = n0 + ni * 8 + 2 * t4;
            if (r < NN) {
                __half2 o = __floats2half2_rn(acc[mi][ni][0], acc[mi][ni][1]);
                *((__half2*)(Out + (size_t)r * NOUT + cc)) = o;
            }
            if (r + 8 < NN) {
                __half2 o = __floats2half2_rn(acc[mi][ni][2], acc[mi][ni][3]);
                *((__half2*)(Out + (size_t)(r + 8) * NOUT + cc)) = o;
            }
        }
    }
}

// ---------------- AGG 1 (chunked): a1h[d]=dd*(hs1[d]*dd + sum hs1[s]*ds) -----
__global__ void k_agg1(int nbase, int ncnt) {
    int gi = (blockIdx.x * blockDim.x + threadIdx.x) >> 5;
    if (gi >= ncnt) return;
    int gw = nbase + gi;
    int lane = threadIdx.x & 31;
    int o0 = g_off[gw], o1 = g_off[gw + 1];
    const uint2* base = (const uint2*)g_hs1;
    float dd = g_dinv[gw];

    uint2 sv = base[(size_t)gw * 32 + lane];
    float2 p0 = h2f2(sv.x), p1 = h2f2(sv.y);
    float a0 = p0.x * dd, a1 = p0.y * dd, a2 = p1.x * dd, a3 = p1.y * dd;

    int i = o0;
    for (; i + 4 <= o1; i += 4) {
        int s0 = g_adj[i], s1 = g_adj[i + 1], s2 = g_adj[i + 2], s3 = g_adj[i + 3];
        uint2 v0 = base[(size_t)s0 * 32 + lane];
        uint2 v1 = base[(size_t)s1 * 32 + lane];
        uint2 v2 = base[(size_t)s2 * 32 + lane];
        uint2 v3 = base[(size_t)s3 * 32 + lane];
        float d0 = g_dinv[s0], d1 = g_dinv[s1], d2 = g_dinv[s2], d3 = g_dinv[s3];
        float2 q;
        q = h2f2(v0.x); a0 += q.x * d0; a1 += q.y * d0;
        q = h2f2(v0.y); a2 += q.x * d0; a3 += q.y * d0;
        q = h2f2(v1.x); a0 += q.x * d1; a1 += q.y * d1;
        q = h2f2(v1.y); a2 += q.x * d1; a3 += q.y * d1;
        q = h2f2(v2.x); a0 += q.x * d2; a1 += q.y * d2;
        q = h2f2(v2.y); a2 += q.x * d2; a3 += q.y * d2;
        q = h2f2(v3.x); a0 += q.x * d3; a1 += q.y * d3;
        q = h2f2(v3.y); a2 += q.x * d3; a3 += q.y * d3;
    }
    for (; i < o1; i++) {
        int s = g_adj[i];
        float ds = g_dinv[s];
        uint2 v = base[(size_t)s * 32 + lane];
        float2 q0 = h2f2(v.x), q1 = h2f2(v.y);
        a0 += q0.x * ds; a1 += q0.y * ds; a2 += q1.x * ds; a3 += q1.y * ds;
    }
    uint2 o;
    o.x = f2h2(a0 * dd, a1 * dd);
    o.y = f2h2(a2 * dd, a3 * dd);
    ((uint2*)g_a1h)[(size_t)gw * 32 + lane] = o;
}

// ---------------- AGG 2: z[d]=dd*(hs2[d]*dd + sum hs2[s]*ds)+b2 (fp16 out) ---
__global__ void k_agg2(const float* __restrict__ b2) {
    int gw = (blockIdx.x * blockDim.x + threadIdx.x) >> 5;
    if (gw >= NN) return;
    int lane = threadIdx.x & 31;
    int o0 = g_off[gw], o1 = g_off[gw + 1];
    const __half2* base = (const __half2*)g_hs2;
    float dd = g_dinv[gw];

    float2 p = __half22float2(base[(size_t)gw * 32 + lane]);
    float a0 = p.x * dd, a1 = p.y * dd;

    int i = o0;
    for (; i + 4 <= o1; i += 4) {
        int s0 = g_adj[i], s1 = g_adj[i + 1], s2 = g_adj[i + 2], s3 = g_adj[i + 3];
        __half2 h0 = base[(size_t)s0 * 32 + lane];
        __half2 h1 = base[(size_t)s1 * 32 + lane];
        __half2 h2 = base[(size_t)s2 * 32 + lane];
        __half2 h3 = base[(size_t)s3 * 32 + lane];
        float d0 = g_dinv[s0], d1 = g_dinv[s1], d2 = g_dinv[s2], d3 = g_dinv[s3];
        float2 q;
        q = __half22float2(h0); a0 += q.x * d0; a1 += q.y * d0;
        q = __half22float2(h1); a0 += q.x * d1; a1 += q.y * d1;
        q = __half22float2(h2); a0 += q.x * d2; a1 += q.y * d2;
        q = __half22float2(h3); a0 += q.x * d3; a1 += q.y * d3;
    }
    for (; i < o1; i++) {
        int s = g_adj[i];
        float ds = g_dinv[s];
        float2 v = __half22float2(base[(size_t)s * 32 + lane]);
        a0 += v.x * ds; a1 += v.y * ds;
    }
    float2 b = ((const float2*)b2)[lane];
    __half2 oz = __floats2half2_rn(a0 * dd + b.x, a1 * dd + b.y);
    ((__half2*)g_z)[(size_t)gw * 32 + lane] = oz;
}

// ---------------- decode (fp16 z gather) -------------------------------------
__global__ void k_decode(const int* __restrict__ pos, const int* __restrict__ neg,
                         float* __restrict__ out) {
    int gw = (blockIdx.x * blockDim.x + threadIdx.x) >> 5;
    if (gw >= 2 * EPP) return;
    int lane = threadIdx.x & 31;
    int a, b;
    if (gw < EPP) { a = pos[gw];        b = pos[EPP + gw]; }
    else          { int j = gw - EPP; a = neg[j]; b = neg[EPP + j]; }
    const __half2* Z = (const __half2*)g_z;
    float2 za = __half22float2(Z[(size_t)a * 32 + lane]);
    float2 zb = __half22float2(Z[(size_t)b * 32 + lane]);
    float p = za.x * zb.x + za.y * zb.y;
#pragma unroll
    for (int o = 16; o > 0; o >>= 1) p += __shfl_xor_sync(0xFFFFFFFFu, p, o);
    if (lane == 0) out[gw] = p;
}

// ---------------- launch ------------------------------------------------------
extern "C" void kernel_launch(void* const* d_in, const int* in_sizes, int n_in,
                              void* d_out, int out_size) {
    const float* x   = (const float*)d_in[0];
    const int*   ei  = (const int*)  d_in[1];
    const int*   pos = (const int*)  d_in[2];
    const int*   neg = (const int*)  d_in[3];
    const float* W1  = (const float*)d_in[4];
    const float* b1  = (const float*)d_in[5];
    const float* W2  = (const float*)d_in[6];
    const float* b2  = (const float*)d_in[7];
    float* out = (float*)d_out;

    const int* src = ei;
    const int* dst = ei + EE;
    const int nb_scan = (NN + 511) / 512;  // 196

    static cudaStream_t s2 = nullptr;
    static cudaEvent_t ev0 = nullptr, ev1 = nullptr, evC = nullptr;
    static cudaEvent_t eA[4] = {nullptr, nullptr, nullptr, nullptr};
    if (!s2) {
        cudaStreamCreateWithFlags(&s2, cudaStreamNonBlocking);
        cudaEventCreateWithFlags(&ev0, cudaEventDisableTiming);
        cudaEventCreateWithFlags(&ev1, cudaEventDisableTiming);
        cudaEventCreateWithFlags(&evC, cudaEventDisableTiming);
        for (int i = 0; i < 4; i++) cudaEventCreateWithFlags(&eA[i], cudaEventDisableTiming);
    }

    // fork at the very start: gemm1 path overlaps the ENTIRE CSR build
    cudaEventRecord(ev0, 0);
    cudaStreamWaitEvent(s2, ev0, 0);

    k_init_deg<<<(NN + 255) / 256, 256>>>();                    // #1 main
    k_count<<<(EE + 255) / 256, 256>>>(dst);                    // #2 main
    k_wprep<<<48, 256, 0, s2>>>(W1, W2);                        // #3 s2
    k_tc<1><<<(NN + 127) / 128, 256, 0, s2>>>(x, nullptr, 0);   // #4 s2 (profiled)
    cudaEventRecord(ev1, s2);

    k_dinv<<<(NN + 255) / 256, 256>>>();
    k_scan1<<<nb_scan, 512>>>();
    k_scan2<<<1, 256>>>(nb_scan);
    k_scan3<<<nb_scan, 512>>>();
    k_fill<<<(EE + 255) / 256, 256>>>(src, dst);

    // join: agg1 needs both CSR (main) and hs1 (s2)
    cudaStreamWaitEvent(0, ev1, 0);

    // ---- agg1 / tc2 chunk pipeline (4 chunks, tile-aligned at 256 rows) ----
    const int cb[5] = {0, 25088, 50176, 75264, 100000};
    for (int i = 0; i < 4; i++) {
        int base = cb[i], cnt = cb[i + 1] - cb[i];
        k_agg1<<<(cnt * 32 + 255) / 256, 256>>>(base, cnt);
        cudaEventRecord(eA[i], 0);
        cudaStreamWaitEvent(s2, eA[i], 0);
        k_tc<2><<<(cnt + 255) / 256, 256, 0, s2>>>(nullptr, b1, base);
    }
    cudaEventRecord(evC, s2);
    cudaStreamWaitEvent(0, evC, 0);

    k_agg2<<<(NN * 32 + 255) / 256, 256>>>(b2);
    k_decode<<<(2 * EPP * 32 + 255) / 256, 256>>>(pos, neg, out);
}

// round 7
// speedup vs baseline: 1.0321x; 1.0321x over previous
#include <cuda_runtime.h>
#include <cuda_fp16.h>
#include <cstdint>

#define NN 100000
#define EE 1600000
#define EPP 200000

// ---------------- scratch (static device globals; no allocation) ------------
// NOTE: relies on zero-init of __device__ globals at module load for the first
// call; k_reset re-zeroes g_deg at the end of every call for the next replay.
__device__ int      g_deg[NN];
__device__ int      g_off[NN + 1];
__device__ int      g_cur[NN];
__device__ int      g_adj[EE];
__device__ float    g_dinv[NN];
__device__ __half   g_hs1[(size_t)NN * 128]; // x@W1 -> prescaled by dinv[row]
__device__ __half   g_a1h[(size_t)NN * 128]; // aggregated layer-1 (fp16)
__device__ __half   g_hs2[(size_t)NN * 64];  // dinv[row]*relu(a1+b1)@W2 (fp16)
__device__ __half   g_z  [(size_t)NN * 64];  // final embeddings (fp16)
__device__ int      g_bsum[256];
__device__ int      g_boff[256];
// packed weights: [n][k2] half2 = (W[2k2][n], W[2k2+1][n]), hi and lo parts
__device__ unsigned g_W1ph[128 * 64], g_W1pl[128 * 64];
__device__ unsigned g_W2ph[64 * 64],  g_W2pl[64 * 64];

// ---------------- fp16 helpers ----------------------------------------------
__device__ __forceinline__ unsigned f2h2(float a, float b) {
    __half2 h = __floats2half2_rn(a, b);
    return *reinterpret_cast<unsigned*>(&h);
}
__device__ __forceinline__ float2 h2f2(unsigned u) {
    __half2 h = *reinterpret_cast<__half2*>(&u);
    return __half22float2(h);
}

__device__ __forceinline__ void mmaf16(float* c, const unsigned* a, unsigned b0, unsigned b1) {
    asm("mma.sync.aligned.m16n8k16.row.col.f32.f16.f16.f32 "
        "{%0,%1,%2,%3}, {%4,%5,%6,%7}, {%8,%9}, {%0,%1,%2,%3};"
        : "+f"(c[0]), "+f"(c[1]), "+f"(c[2]), "+f"(c[3])
        : "r"(a[0]), "r"(a[1]), "r"(a[2]), "r"(a[3]), "r"(b0), "r"(b1));
}

__device__ __forceinline__ void ldsm4(unsigned* r, unsigned addr) {
    asm volatile("ldmatrix.sync.aligned.m8n8.x4.shared.b16 {%0,%1,%2,%3}, [%4];"
        : "=r"(r[0]), "=r"(r[1]), "=r"(r[2]), "=r"(r[3]) : "r"(addr));
}

// ---------------- degree / CSR build ----------------------------------------
__global__ void k_count(const int* __restrict__ dst) {
    int e = blockIdx.x * blockDim.x + threadIdx.x;
    if (e < EE) atomicAdd(&g_deg[dst[e]], 1);
}

// fused: block scan of deg + dinv computation
__global__ void k_scanA() {
    __shared__ int s[512];
    int t = threadIdx.x;
    int idx = blockIdx.x * 512 + t;
    int v = (idx < NN) ? g_deg[idx] : 0;
    if (idx < NN) g_dinv[idx] = rsqrtf((float)(v + 1));  // +1 self loop
    s[t] = v;
    __syncthreads();
#pragma unroll
    for (int o = 1; o < 512; o <<= 1) {
        int x = (t >= o) ? s[t - o] : 0;
        __syncthreads();
        s[t] += x;
        __syncthreads();
    }
    if (idx < NN) g_off[idx] = s[t] - v;
    if (t == 511) g_bsum[blockIdx.x] = s[511];
}

__global__ void k_scan2(int nb) {
    __shared__ int s[256];
    int t = threadIdx.x;
    int v = (t < nb) ? g_bsum[t] : 0;
    s[t] = v;
    __syncthreads();
#pragma unroll
    for (int o = 1; o < 256; o <<= 1) {
        int x = (t >= o) ? s[t - o] : 0;
        __syncthreads();
        s[t] += x;
        __syncthreads();
    }
    if (t < nb) g_boff[t] = s[t] - v;
}

__global__ void k_scan3() {
    int t = threadIdx.x;
    int idx = blockIdx.x * 512 + t;
    if (idx < NN) {
        int val = g_off[idx] + g_boff[blockIdx.x];
        g_off[idx] = val;
        g_cur[idx] = val;
        if (idx == 0) g_off[NN] = EE;
    }
}

__global__ void k_fill(const int* __restrict__ src, const int* __restrict__ dst) {
    int e = blockIdx.x * blockDim.x + threadIdx.x;
    if (e < EE) {
        int d = dst[e];
        int p = atomicAdd(&g_cur[d], 1);
        g_adj[p] = src[e];
    }
}

// zero g_deg for the NEXT call (off critical path)
__global__ void k_reset() {
    int i = blockIdx.x * blockDim.x + threadIdx.x;
    if (i < NN) g_deg[i] = 0;
}

// ---------------- weight hi/lo split + transpose-pack ------------------------
__global__ void k_wprep(const float* __restrict__ W1, const float* __restrict__ W2) {
    int i = blockIdx.x * blockDim.x + threadIdx.x;
    if (i < 128 * 64) {
        int n = i >> 6, k2 = i & 63;
        float w0 = W1[(2 * k2) * 128 + n];
        float w1 = W1[(2 * k2 + 1) * 128 + n];
        unsigned h = f2h2(w0, w1);
        float2 hf = h2f2(h);
        g_W1ph[i] = h;
        g_W1pl[i] = f2h2(w0 - hf.x, w1 - hf.y);
    } else if (i < 128 * 64 + 64 * 64) {
        int j = i - 128 * 64;
        int n = j >> 6, k2 = j & 63;
        float w0 = W2[(2 * k2) * 64 + n];
        float w1 = W2[(2 * k2 + 1) * 64 + n];
        unsigned h = f2h2(w0, w1);
        float2 hf = h2f2(h);
        g_W2ph[j] = h;
        g_W2pl[j] = f2h2(w0 - hf.x, w1 - hf.y);
    }
}

// ---------------- in-place prescale: hs1[r] *= dinv[r] -----------------------
__global__ void k_scale1() {
    int idx = blockIdx.x * blockDim.x + threadIdx.x;   // NN*32 lane-slots
    int gw = idx >> 5, lane = idx & 31;
    if (gw >= NN) return;
    float dd = g_dinv[gw];
    uint2* p = (uint2*)g_hs1 + (size_t)gw * 32 + lane;
    uint2 v = *p;
    float2 q0 = h2f2(v.x), q1 = h2f2(v.y);
    v.x = f2h2(q0.x * dd, q0.y * dd);
    v.y = f2h2(q1.x * dd, q1.y * dd);
    *p = v;
}

// ---------------- tensor-core GEMM, ldmatrix frags ---------------------------
// LAYER 1: hs1[NN,128] = x @ W1 (fp32 in, 3-term hi/lo split), MT=128, NOUT=128
// LAYER 2: hs2[NN,64] = dinv[r]*relu(a1h+b1)@W2 (fp16 A, 2-term), MT=256, NOUT=64
template<int LAYER>
__global__ __launch_bounds__(256) void k_tc(const float* __restrict__ Xsrc,
                                            const float* __restrict__ bias,
                                            int rowbase) {
    constexpr int MT   = (LAYER == 1) ? 128 : 256;
    constexpr int NOUT = (LAYER == 1) ? 128 : 64;

    const unsigned* Wph = (LAYER == 1) ? g_W1ph : g_W2ph;
    const unsigned* Wpl = (LAYER == 1) ? g_W1pl : g_W2pl;
    __half*         Out = (LAYER == 1) ? g_hs1 : g_hs2;

    __shared__ unsigned Ah[MT * 12];
    __shared__ unsigned Al[(LAYER == 1) ? MT * 12 : 12];   // unused for L2
    __shared__ unsigned Bh[NOUT * 12], Bl[NOUT * 12];

    const int tid  = threadIdx.x;
    const int lane = tid & 31;
    const int wid  = tid >> 5;
    const int g    = lane >> 2;
    const int t4   = lane & 3;
    const int row0 = rowbase + blockIdx.x * MT;
    const int warpM = (LAYER == 1) ? (wid >> 1) * 32 : wid * 32;
    const int n0    = (LAYER == 1) ? (wid & 1) * 64 : 0;

    const unsigned sAh = (unsigned)__cvta_generic_to_shared(Ah);
    const unsigned sAl = (unsigned)__cvta_generic_to_shared(Al);
    const unsigned sBh = (unsigned)__cvta_generic_to_shared(Bh);
    const unsigned sBl = (unsigned)__cvta_generic_to_shared(Bl);
    const int l7 = lane & 7;
    const int r8 = (lane >> 3) & 1;
    const int w4 = (lane >> 4) * 4;
    unsigned aAddrOff[2];
#pragma unroll
    for (int mi = 0; mi < 2; mi++) {
        int row = warpM + mi * 16 + l7 + r8 * 8;
        aAddrOff[mi] = (unsigned)((row * 12 + w4) * 4);
    }
    unsigned bAddr[4], blAddr[4];
    const int bw4 = ((lane >> 3) & 1) * 4;
    const int bn8 = (lane >= 16) ? 8 : 0;
#pragma unroll
    for (int nn = 0; nn < 4; nn++) {
        int nrow = n0 + nn * 16 + l7 + bn8;
        unsigned off = (unsigned)((nrow * 12 + bw4) * 4);
        bAddr[nn]  = sBh + off;
        blAddr[nn] = sBl + off;
    }

    float acc[2][8][4];
#pragma unroll
    for (int mi = 0; mi < 2; mi++)
#pragma unroll
        for (int ni = 0; ni < 8; ni++)
#pragma unroll
            for (int q = 0; q < 4; q++) acc[mi][ni][q] = 0.f;

#pragma unroll 1
    for (int kc = 0; kc < 8; kc++) {
        const int kbase = kc * 16;
        if (LAYER == 1) {
#pragma unroll
            for (int j = 0; j < MT / 64; j++) {
                int idx = tid + 256 * j;
                int r = idx >> 2, c4 = idx & 3;
                int gr = row0 + r;
                float4 v = {0.f, 0.f, 0.f, 0.f};
                if (gr < NN)
                    v = ((const float4*)(Xsrc + (size_t)gr * 128 + kbase))[c4];
                unsigned h01 = f2h2(v.x, v.y), h23 = f2h2(v.z, v.w);
                float2 f01 = h2f2(h01), f23 = h2f2(h23);
                unsigned l01 = f2h2(v.x - f01.x, v.y - f01.y);
                unsigned l23 = f2h2(v.z - f23.x, v.w - f23.y);
                *(uint2*)&Ah[r * 12 + c4 * 2] = make_uint2(h01, h23);
                *(uint2*)&Al[r * 12 + c4 * 2] = make_uint2(l01, l23);
            }
        } else {
            int r = tid;
            int gr = row0 + r;
            uint4 u0 = {0,0,0,0}, u1 = {0,0,0,0};
            if (gr < NN) {
                const uint4* p = (const uint4*)(g_a1h + (size_t)gr * 128 + kbase);
                u0 = p[0]; u1 = p[1];
                const float2* bp = (const float2*)(bias + kbase);
                unsigned* uw = &u0.x;
#pragma unroll
                for (int w = 0; w < 4; w++) {
                    float2 f = h2f2(uw[w]); float2 b = bp[w];
                    uw[w] = f2h2(fmaxf(f.x + b.x, 0.f), fmaxf(f.y + b.y, 0.f));
                }
                unsigned* uw1 = &u1.x;
#pragma unroll
                for (int w = 0; w < 4; w++) {
                    float2 f = h2f2(uw1[w]); float2 b = bp[w + 4];
                    uw1[w] = f2h2(fmaxf(f.x + b.x, 0.f), fmaxf(f.y + b.y, 0.f));
                }
            }
            *(uint4*)&Ah[r * 12]     = u0;
            *(uint4*)&Ah[r * 12 + 4] = u1;
        }
#pragma unroll
        for (int j = 0; j < NOUT / 64; j++) {
            int idx = tid + 256 * j;
            int n = idx >> 2, jp = (idx & 3) * 2;
            uint2 vh = *(const uint2*)&Wph[n * 64 + kc * 8 + jp];
            uint2 vl = *(const uint2*)&Wpl[n * 64 + kc * 8 + jp];
            *(uint2*)&Bh[n * 12 + jp] = vh;
            *(uint2*)&Bl[n * 12 + jp] = vl;
        }
        __syncthreads();

        unsigned ah[2][4], al[2][4];
#pragma unroll
        for (int mi = 0; mi < 2; mi++) {
            ldsm4(ah[mi], sAh + aAddrOff[mi]);
            if (LAYER == 1) ldsm4(al[mi], sAl + aAddrOff[mi]);
        }
#pragma unroll
        for (int nn = 0; nn < 4; nn++) {
            unsigned bh[4], bl[4];
            ldsm4(bh, bAddr[nn]);
            ldsm4(bl, blAddr[nn]);
#pragma unroll
            for (int p = 0; p < 2; p++) {
                int ni = nn * 2 + p;
                unsigned b0 = bh[p * 2], b1 = bh[p * 2 + 1];
                unsigned c0 = bl[p * 2], c1 = bl[p * 2 + 1];
#pragma unroll
                for (int mi = 0; mi < 2; mi++) {
                    mmaf16(acc[mi][ni], ah[mi], b0, b1);
                    if (LAYER == 1) mmaf16(acc[mi][ni], al[mi], b0, b1);
                    mmaf16(acc[mi][ni], ah[mi], c0, c1);
                }
            }
        }
        __syncthreads();
    }

    // epilogue: fp16 output; LAYER 2 prescales by dinv[row]
#pragma unroll
    for (int mi = 0; mi < 2; mi++) {
#pragma unroll
        for (int ni = 0; ni < 8; ni++) {
            int r  = row0 + warpM + mi * 16 + g;
            int cc = n0 + ni * 8 + 2 * t4;
            if (r < NN) {
                float s = (LAYER == 2) ? g_dinv[r] : 1.f;
                __half2 o = __floats2half2_rn(acc[mi][ni][0] * s, acc[mi][ni][1] * s);
                *((__half2*)(Out + (size_t)r * NOUT + cc)) = o;
            }
            if (r + 8 < NN) {
                float s = (LAYER == 2) ? g_dinv[r + 8] : 1.f;
                __half2 o = __floats2half2_rn(acc[mi][ni][2] * s, acc[mi][ni][3] * s);
                *((__half2*)(Out + (size_t)(r + 8) * NOUT + cc)) = o;
            }
        }
    }
}

// ---------------- AGG 1: a1h[d] = dd * sum of prescaled rows -----------------
// hs1 rows already carry dinv[src]; inner loop is pure adds; adj read via int4.
__global__ void k_agg1() {
    int gw = (blockIdx.x * blockDim.x + threadIdx.x) >> 5;
    if (gw >= NN) return;
    int lane = threadIdx.x & 31;
    int o0 = g_off[gw], o1 = g_off[gw + 1];
    const uint2* base = (const uint2*)g_hs1;
    float dd = g_dinv[gw];

    uint2 sv = base[(size_t)gw * 32 + lane];
    float2 p0 = h2f2(sv.x), p1 = h2f2(sv.y);
    float a0 = p0.x, a1 = p0.y, a2 = p1.x, a3 = p1.y;

    int i = o0;
    // align to 4 for int4 adjacency loads
    for (; i < o1 && (i & 3); i++) {
        int s = g_adj[i];
        uint2 v = base[(size_t)s * 32 + lane];
        float2 q0 = h2f2(v.x), q1 = h2f2(v.y);
        a0 += q0.x; a1 += q0.y; a2 += q1.x; a3 += q1.y;
    }
    for (; i + 4 <= o1; i += 4) {
        int4 s4 = *(const int4*)(g_adj + i);
        uint2 v0 = base[(size_t)s4.x * 32 + lane];
        uint2 v1 = base[(size_t)s4.y * 32 + lane];
        uint2 v2 = base[(size_t)s4.z * 32 + lane];
        uint2 v3 = base[(size_t)s4.w * 32 + lane];
        float2 q;
        q = h2f2(v0.x); a0 += q.x; a1 += q.y;
        q = h2f2(v0.y); a2 += q.x; a3 += q.y;
        q = h2f2(v1.x); a0 += q.x; a1 += q.y;
        q = h2f2(v1.y); a2 += q.x; a3 += q.y;
        q = h2f2(v2.x); a0 += q.x; a1 += q.y;
        q = h2f2(v2.y); a2 += q.x; a3 += q.y;
        q = h2f2(v3.x); a0 += q.x; a1 += q.y;
        q = h2f2(v3.y); a2 += q.x; a3 += q.y;
    }
    for (; i < o1; i++) {
        int s = g_adj[i];
        uint2 v = base[(size_t)s * 32 + lane];
        float2 q0 = h2f2(v.x), q1 = h2f2(v.y);
        a0 += q0.x; a1 += q0.y; a2 += q1.x; a3 += q1.y;
    }
    uint2 o;
    o.x = f2h2(a0 * dd, a1 * dd);
    o.y = f2h2(a2 * dd, a3 * dd);
    ((uint2*)g_a1h)[(size_t)gw * 32 + lane] = o;
}

// ---------------- AGG 2: z[d] = dd * sum of prescaled hs2 rows + b2 ----------
__global__ void k_agg2(const float* __restrict__ b2) {
    int gw = (blockIdx.x * blockDim.x + threadIdx.x) >> 5;
    if (gw >= NN) return;
    int lane = threadIdx.x & 31;
    int o0 = g_off[gw], o1 = g_off[gw + 1];
    const __half2* base = (const __half2*)g_hs2;
    float dd = g_dinv[gw];

    float2 p = __half22float2(base[(size_t)gw * 32 + lane]);
    float a0 = p.x, a1 = p.y;

    int i = o0;
    for (; i < o1 && (i & 3); i++) {
        float2 v = __half22float2(base[(size_t)g_adj[i] * 32 + lane]);
        a0 += v.x; a1 += v.y;
    }
    for (; i + 4 <= o1; i += 4) {
        int4 s4 = *(const int4*)(g_adj + i);
        float2 v0 = __half22float2(base[(size_t)s4.x * 32 + lane]);
        float2 v1 = __half22float2(base[(size_t)s4.y * 32 + lane]);
        float2 v2 = __half22float2(base[(size_t)s4.z * 32 + lane]);
        float2 v3 = __half22float2(base[(size_t)s4.w * 32 + lane]);
        a0 += v0.x + v1.x + v2.x + v3.x;
        a1 += v0.y + v1.y + v2.y + v3.y;
    }
    for (; i < o1; i++) {
        float2 v = __half22float2(base[(size_t)g_adj[i] * 32 + lane]);
        a0 += v.x; a1 += v.y;
    }
    float2 b = ((const float2*)b2)[lane];
    __half2 oz = __floats2half2_rn(a0 * dd + b.x, a1 * dd + b.y);
    ((__half2*)g_z)[(size_t)gw * 32 + lane] = oz;
}

// ---------------- decode (fp16 z gather) -------------------------------------
__global__ void k_decode(const int* __restrict__ pos, const int* __restrict__ neg,
                         float* __restrict__ out) {
    int gw = (blockIdx.x * blockDim.x + threadIdx.x) >> 5;
    if (gw >= 2 * EPP) return;
    int lane = threadIdx.x & 31;
    int a, b;
    if (gw < EPP) { a = pos[gw];        b = pos[EPP + gw]; }
    else          { int j = gw - EPP; a = neg[j]; b = neg[EPP + j]; }
    const __half2* Z = (const __half2*)g_z;
    float2 za = __half22float2(Z[(size_t)a * 32 + lane]);
    float2 zb = __half22float2(Z[(size_t)b * 32 + lane]);
    float p = za.x * zb.x + za.y * zb.y;
#pragma unroll
    for (int o = 16; o > 0; o >>= 1) p += __shfl_xor_sync(0xFFFFFFFFu, p, o);
    if (lane == 0) out[gw] = p;
}

// ---------------- launch ------------------------------------------------------
extern "C" void kernel_launch(void* const* d_in, const int* in_sizes, int n_in,
                              void* d_out, int out_size) {
    const float* x   = (const float*)d_in[0];
    const int*   ei  = (const int*)  d_in[1];
    const int*   pos = (const int*)  d_in[2];
    const int*   neg = (const int*)  d_in[3];
    const float* W1  = (const float*)d_in[4];
    const float* b1  = (const float*)d_in[5];
    const float* W2  = (const float*)d_in[6];
    const float* b2  = (const float*)d_in[7];
    float* out = (float*)d_out;

    const int* src = ei;
    const int* dst = ei + EE;
    const int nb_scan = (NN + 511) / 512;  // 196

    static cudaStream_t s2 = nullptr;
    static cudaEvent_t ev0 = nullptr, evD = nullptr, ev1 = nullptr;
    if (!s2) {
        cudaStreamCreateWithFlags(&s2, cudaStreamNonBlocking);
        cudaEventCreateWithFlags(&ev0, cudaEventDisableTiming);
        cudaEventCreateWithFlags(&evD, cudaEventDisableTiming);
        cudaEventCreateWithFlags(&ev1, cudaEventDisableTiming);
    }

    // fork at the very start: gemm1 path overlaps the CSR build
    cudaEventRecord(ev0, 0);
    cudaStreamWaitEvent(s2, ev0, 0);

    k_count<<<(EE + 255) / 256, 256>>>(dst);                    // #0 main
    k_wprep<<<48, 256, 0, s2>>>(W1, W2);                        // #1 s2
    k_scanA<<<nb_scan, 512>>>();                                // #2 main (scan+dinv)
    k_tc<1><<<(NN + 127) / 128, 256, 0, s2>>>(x, nullptr, 0);   // #3 s2 (profiled)
    cudaEventRecord(evD, 0);                                    // dinv ready

    k_scan2<<<1, 256>>>(nb_scan);                               // #4 main
    k_scan3<<<nb_scan, 512>>>();                                // #5 main
    k_fill<<<(EE + 255) / 256, 256>>>(src, dst);                // #6 main
    k_reset<<<(NN + 255) / 256, 256>>>();                       // #7 main (next-call deg=0)

    // s2: prescale hs1 once dinv and tc1 are done
    cudaStreamWaitEvent(s2, evD, 0);
    k_scale1<<<(NN * 32 + 255) / 256, 256, 0, s2>>>();          // #8 s2
    cudaEventRecord(ev1, s2);

    // join: agg1 needs CSR (main, in-order) + prescaled hs1 (s2)
    cudaStreamWaitEvent(0, ev1, 0);

    k_agg1<<<(NN * 32 + 255) / 256, 256>>>();                   // #9
    k_tc<2><<<(NN + 255) / 256, 256>>>(nullptr, b1, 0);         // #10
    k_agg2<<<(NN * 32 + 255) / 256, 256>>>(b2);                 // #11
    k_decode<<<(2 * EPP * 32 + 255) / 256, 256>>>(pos, neg, out); // #12
}

// round 8
// speedup vs baseline: 1.0662x; 1.0330x over previous
#include <cuda_runtime.h>
#include <cuda_fp16.h>
#include <cstdint>

#define NN 100000
#define EE 1600000
#define EPP 200000

// ---------------- scratch (static device globals; no allocation) ------------
// Zero-init at module load covers call #1; k_reset re-zeroes g_deg each call.
__device__ int      g_deg[NN];
__device__ int      g_off[NN + 1];
__device__ int      g_cur[NN];
__device__ int      g_adj[EE];
__device__ float    g_dinv[NN];
__device__ __half   g_hs1[(size_t)NN * 128]; // x@W1 -> prescaled by dinv[row]
__device__ __half   g_a1h[(size_t)NN * 128]; // aggregated layer-1 (fp16)
__device__ __half   g_hs2[(size_t)NN * 64];  // dinv[row]*relu(a1+b1)@W2 (fp16)
__device__ __half   g_z  [(size_t)NN * 64];  // final embeddings (fp16)
__device__ int      g_bsum[256];
__device__ int      g_boff[256];
// packed weights: [n][k2] half2 = (W[2k2][n], W[2k2+1][n])
__device__ unsigned g_W1p[128 * 64];
__device__ unsigned g_W2p[64 * 64];

// ---------------- fp16 helpers ----------------------------------------------
__device__ __forceinline__ unsigned f2h2(float a, float b) {
    __half2 h = __floats2half2_rn(a, b);
    return *reinterpret_cast<unsigned*>(&h);
}
__device__ __forceinline__ float2 h2f2(unsigned u) {
    __half2 h = *reinterpret_cast<__half2*>(&u);
    return __half22float2(h);
}

__device__ __forceinline__ void mmaf16(float* c, const unsigned* a, unsigned b0, unsigned b1) {
    asm("mma.sync.aligned.m16n8k16.row.col.f32.f16.f16.f32 "
        "{%0,%1,%2,%3}, {%4,%5,%6,%7}, {%8,%9}, {%0,%1,%2,%3};"
        : "+f"(c[0]), "+f"(c[1]), "+f"(c[2]), "+f"(c[3])
        : "r"(a[0]), "r"(a[1]), "r"(a[2]), "r"(a[3]), "r"(b0), "r"(b1));
}

__device__ __forceinline__ void ldsm4(unsigned* r, unsigned addr) {
    asm volatile("ldmatrix.sync.aligned.m8n8.x4.shared.b16 {%0,%1,%2,%3}, [%4];"
        : "=r"(r[0]), "=r"(r[1]), "=r"(r[2]), "=r"(r[3]) : "r"(addr));
}

// ---------------- degree / CSR build ----------------------------------------
__global__ void k_count(const int* __restrict__ dst) {
    int e = blockIdx.x * blockDim.x + threadIdx.x;
    if (e < EE) atomicAdd(&g_deg[dst[e]], 1);
}

// fused: block scan of deg + dinv computation
__global__ void k_scanA() {
    __shared__ int s[512];
    int t = threadIdx.x;
    int idx = blockIdx.x * 512 + t;
    int v = (idx < NN) ? g_deg[idx] : 0;
    if (idx < NN) g_dinv[idx] = rsqrtf((float)(v + 1));  // +1 self loop
    s[t] = v;
    __syncthreads();
#pragma unroll
    for (int o = 1; o < 512; o <<= 1) {
        int x = (t >= o) ? s[t - o] : 0;
        __syncthreads();
        s[t] += x;
        __syncthreads();
    }
    if (idx < NN) g_off[idx] = s[t] - v;
    if (t == 511) g_bsum[blockIdx.x] = s[511];
}

__global__ void k_scan2(int nb) {
    __shared__ int s[256];
    int t = threadIdx.x;
    int v = (t < nb) ? g_bsum[t] : 0;
    s[t] = v;
    __syncthreads();
#pragma unroll
    for (int o = 1; o < 256; o <<= 1) {
        int x = (t >= o) ? s[t - o] : 0;
        __syncthreads();
        s[t] += x;
        __syncthreads();
    }
    if (t < nb) g_boff[t] = s[t] - v;
}

__global__ void k_scan3() {
    int t = threadIdx.x;
    int idx = blockIdx.x * 512 + t;
    if (idx < NN) {
        int val = g_off[idx] + g_boff[blockIdx.x];
        g_off[idx] = val;
        g_cur[idx] = val;
        if (idx == 0) g_off[NN] = EE;
    }
}

__global__ void k_fill(const int* __restrict__ src, const int* __restrict__ dst) {
    int e = blockIdx.x * blockDim.x + threadIdx.x;
    if (e < EE) {
        int d = dst[e];
        int p = atomicAdd(&g_cur[d], 1);
        g_adj[p] = src[e];
    }
}

// zero g_deg for the NEXT call (runs on s2, off critical path)
__global__ void k_reset() {
    int i = blockIdx.x * blockDim.x + threadIdx.x;
    if (i < NN) g_deg[i] = 0;
}

// ---------------- weight fp16 transpose-pack ---------------------------------
__global__ void k_wprep(const float* __restrict__ W1, const float* __restrict__ W2) {
    int i = blockIdx.x * blockDim.x + threadIdx.x;
    if (i < 128 * 64) {
        int n = i >> 6, k2 = i & 63;
        g_W1p[i] = f2h2(W1[(2 * k2) * 128 + n], W1[(2 * k2 + 1) * 128 + n]);
    } else if (i < 128 * 64 + 64 * 64) {
        int j = i - 128 * 64;
        int n = j >> 6, k2 = j & 63;
        g_W2p[j] = f2h2(W2[(2 * k2) * 64 + n], W2[(2 * k2 + 1) * 64 + n]);
    }
}

// ---------------- in-place prescale: hs1[r] *= dinv[r] -----------------------
__global__ void k_scale1() {
    int idx = blockIdx.x * blockDim.x + threadIdx.x;   // NN*32 lane-slots
    int gw = idx >> 5, lane = idx & 31;
    if (gw >= NN) return;
    float dd = g_dinv[gw];
    uint2* p = (uint2*)g_hs1 + (size_t)gw * 32 + lane;
    uint2 v = *p;
    float2 q0 = h2f2(v.x), q1 = h2f2(v.y);
    v.x = f2h2(q0.x * dd, q0.y * dd);
    v.y = f2h2(q1.x * dd, q1.y * dd);
    *p = v;
}

// ---------------- tensor-core GEMM, pure fp16, ldmatrix frags ----------------
// LAYER 1: hs1[NN,128] = fp16(x) @ fp16(W1), MT=128, NOUT=128
// LAYER 2: hs2[NN,64]  = dinv[r]*relu(a1h+b1) @ fp16(W2), MT=256, NOUT=64
template<int LAYER>
__global__ __launch_bounds__(256) void k_tc(const float* __restrict__ Xsrc,
                                            const float* __restrict__ bias,
                                            int rowbase) {
    constexpr int MT   = (LAYER == 1) ? 128 : 256;
    constexpr int NOUT = (LAYER == 1) ? 128 : 64;

    const unsigned* Wp  = (LAYER == 1) ? g_W1p : g_W2p;
    __half*         Out = (LAYER == 1) ? g_hs1 : g_hs2;

    __shared__ unsigned Ah[MT * 12];
    __shared__ unsigned Bh[NOUT * 12];

    const int tid  = threadIdx.x;
    const int lane = tid & 31;
    const int wid  = tid >> 5;
    const int g    = lane >> 2;
    const int t4   = lane & 3;
    const int row0 = rowbase + blockIdx.x * MT;
    const int warpM = (LAYER == 1) ? (wid >> 1) * 32 : wid * 32;
    const int n0    = (LAYER == 1) ? (wid & 1) * 64 : 0;

    const unsigned sAh = (unsigned)__cvta_generic_to_shared(Ah);
    const unsigned sBh = (unsigned)__cvta_generic_to_shared(Bh);
    const int l7 = lane & 7;
    const int r8 = (lane >> 3) & 1;
    const int w4 = (lane >> 4) * 4;
    unsigned aAddr[2];
#pragma unroll
    for (int mi = 0; mi < 2; mi++) {
        int row = warpM + mi * 16 + l7 + r8 * 8;
        aAddr[mi] = sAh + (unsigned)((row * 12 + w4) * 4);
    }
    unsigned bAddr[4];
    const int bw4 = ((lane >> 3) & 1) * 4;
    const int bn8 = (lane >= 16) ? 8 : 0;
#pragma unroll
    for (int nn = 0; nn < 4; nn++) {
        int nrow = n0 + nn * 16 + l7 + bn8;
        bAddr[nn] = sBh + (unsigned)((nrow * 12 + bw4) * 4);
    }

    float acc[2][8][4];
#pragma unroll
    for (int mi = 0; mi < 2; mi++)
#pragma unroll
        for (int ni = 0; ni < 8; ni++)
#pragma unroll
            for (int q = 0; q < 4; q++) acc[mi][ni][q] = 0.f;

#pragma unroll 1
    for (int kc = 0; kc < 8; kc++) {
        const int kbase = kc * 16;
        if (LAYER == 1) {
#pragma unroll
            for (int j = 0; j < MT / 64; j++) {
                int idx = tid + 256 * j;
                int r = idx >> 2, c4 = idx & 3;
                int gr = row0 + r;
                float4 v = {0.f, 0.f, 0.f, 0.f};
                if (gr < NN)
                    v = ((const float4*)(Xsrc + (size_t)gr * 128 + kbase))[c4];
                *(uint2*)&Ah[r * 12 + c4 * 2] =
                    make_uint2(f2h2(v.x, v.y), f2h2(v.z, v.w));
            }
        } else {
            int r = tid;
            int gr = row0 + r;
            uint4 u0 = {0,0,0,0}, u1 = {0,0,0,0};
            if (gr < NN) {
                const uint4* p = (const uint4*)(g_a1h + (size_t)gr * 128 + kbase);
                u0 = p[0]; u1 = p[1];
                const float2* bp = (const float2*)(bias + kbase);
                unsigned* uw = &u0.x;
#pragma unroll
                for (int w = 0; w < 4; w++) {
                    float2 f = h2f2(uw[w]); float2 b = bp[w];
                    uw[w] = f2h2(fmaxf(f.x + b.x, 0.f), fmaxf(f.y + b.y, 0.f));
                }
                unsigned* uw1 = &u1.x;
#pragma unroll
                for (int w = 0; w < 4; w++) {
                    float2 f = h2f2(uw1[w]); float2 b = bp[w + 4];
                    uw1[w] = f2h2(fmaxf(f.x + b.x, 0.f), fmaxf(f.y + b.y, 0.f));
                }
            }
            *(uint4*)&Ah[r * 12]     = u0;
            *(uint4*)&Ah[r * 12 + 4] = u1;
        }
#pragma unroll
        for (int j = 0; j < NOUT / 64; j++) {
            int idx = tid + 256 * j;
            int n = idx >> 2, jp = (idx & 3) * 2;
            *(uint2*)&Bh[n * 12 + jp] = *(const uint2*)&Wp[n * 64 + kc * 8 + jp];
        }
        __syncthreads();

        unsigned ah[2][4];
#pragma unroll
        for (int mi = 0; mi < 2; mi++) ldsm4(ah[mi], aAddr[mi]);
#pragma unroll
        for (int nn = 0; nn < 4; nn++) {
            unsigned bh[4];
            ldsm4(bh, bAddr[nn]);
#pragma unroll
            for (int p = 0; p < 2; p++) {
                int ni = nn * 2 + p;
#pragma unroll
                for (int mi = 0; mi < 2; mi++)
                    mmaf16(acc[mi][ni], ah[mi], bh[p * 2], bh[p * 2 + 1]);
            }
        }
        __syncthreads();
    }

    // epilogue: fp16 output; LAYER 2 prescales by dinv[row]
#pragma unroll
    for (int mi = 0; mi < 2; mi++) {
#pragma unroll
        for (int ni = 0; ni < 8; ni++) {
            int r  = row0 + warpM + mi * 16 + g;
            int cc = n0 + ni * 8 + 2 * t4;
            if (r < NN) {
                float s = (LAYER == 2) ? g_dinv[r] : 1.f;
                __half2 o = __floats2half2_rn(acc[mi][ni][0] * s, acc[mi][ni][1] * s);
                *((__half2*)(Out + (size_t)r * NOUT + cc)) = o;
            }
            if (r + 8 < NN) {
                float s = (LAYER == 2) ? g_dinv[r + 8] : 1.f;
                __half2 o = __floats2half2_rn(acc[mi][ni][2] * s, acc[mi][ni][3] * s);
                *((__half2*)(Out + (size_t)(r + 8) * NOUT + cc)) = o;
            }
        }
    }
}

// ---------------- AGG 1: a1h[d] = dd * sum of prescaled rows -----------------
__global__ void k_agg1() {
    int gw = (blockIdx.x * blockDim.x + threadIdx.x) >> 5;
    if (gw >= NN) return;
    int lane = threadIdx.x & 31;
    int o0 = g_off[gw], o1 = g_off[gw + 1];
    const uint2* base = (const uint2*)g_hs1;
    float dd = g_dinv[gw];

    uint2 sv = base[(size_t)gw * 32 + lane];
    float2 p0 = h2f2(sv.x), p1 = h2f2(sv.y);
    float a0 = p0.x, a1 = p0.y, a2 = p1.x, a3 = p1.y;

    int i = o0;
    for (; i < o1 && (i & 3); i++) {
        int s = g_adj[i];
        uint2 v = base[(size_t)s * 32 + lane];
        float2 q0 = h2f2(v.x), q1 = h2f2(v.y);
        a0 += q0.x; a1 += q0.y; a2 += q1.x; a3 += q1.y;
    }
    for (; i + 4 <= o1; i += 4) {
        int4 s4 = *(const int4*)(g_adj + i);
        uint2 v0 = base[(size_t)s4.x * 32 + lane];
        uint2 v1 = base[(size_t)s4.y * 32 + lane];
        uint2 v2 = base[(size_t)s4.z * 32 + lane];
        uint2 v3 = base[(size_t)s4.w * 32 + lane];
        float2 q;
        q = h2f2(v0.x); a0 += q.x; a1 += q.y;
        q = h2f2(v0.y); a2 += q.x; a3 += q.y;
        q = h2f2(v1.x); a0 += q.x; a1 += q.y;
        q = h2f2(v1.y); a2 += q.x; a3 += q.y;
        q = h2f2(v2.x); a0 += q.x; a1 += q.y;
        q = h2f2(v2.y); a2 += q.x; a3 += q.y;
        q = h2f2(v3.x); a0 += q.x; a1 += q.y;
        q = h2f2(v3.y); a2 += q.x; a3 += q.y;
    }
    for (; i < o1; i++) {
        int s = g_adj[i];
        uint2 v = base[(size_t)s * 32 + lane];
        float2 q0 = h2f2(v.x), q1 = h2f2(v.y);
        a0 += q0.x; a1 += q0.y; a2 += q1.x; a3 += q1.y;
    }
    uint2 o;
    o.x = f2h2(a0 * dd, a1 * dd);
    o.y = f2h2(a2 * dd, a3 * dd);
    ((uint2*)g_a1h)[(size_t)gw * 32 + lane] = o;
}

// ---------------- AGG 2: z[d] = dd * sum of prescaled hs2 rows + b2 ----------
__global__ void k_agg2(const float* __restrict__ b2) {
    int gw = (blockIdx.x * blockDim.x + threadIdx.x) >> 5;
    if (gw >= NN) return;
    int lane = threadIdx.x & 31;
    int o0 = g_off[gw], o1 = g_off[gw + 1];
    const __half2* base = (const __half2*)g_hs2;
    float dd = g_dinv[gw];

    float2 p = __half22float2(base[(size_t)gw * 32 + lane]);
    float a0 = p.x, a1 = p.y;

    int i = o0;
    for (; i < o1 && (i & 3); i++) {
        float2 v = __half22float2(base[(size_t)g_adj[i] * 32 + lane]);
        a0 += v.x; a1 += v.y;
    }
    for (; i + 4 <= o1; i += 4) {
        int4 s4 = *(const int4*)(g_adj + i);
        float2 v0 = __half22float2(base[(size_t)s4.x * 32 + lane]);
        float2 v1 = __half22float2(base[(size_t)s4.y * 32 + lane]);
        float2 v2 = __half22float2(base[(size_t)s4.z * 32 + lane]);
        float2 v3 = __half22float2(base[(size_t)s4.w * 32 + lane]);
        a0 += v0.x + v1.x + v2.x + v3.x;
        a1 += v0.y + v1.y + v2.y + v3.y;
    }
    for (; i < o1; i++) {
        float2 v = __half22float2(base[(size_t)g_adj[i] * 32 + lane]);
        a0 += v.x; a1 += v.y;
    }
    float2 b = ((const float2*)b2)[lane];
    __half2 oz = __floats2half2_rn(a0 * dd + b.x, a1 * dd + b.y);
    ((__half2*)g_z)[(size_t)gw * 32 + lane] = oz;
}

// ---------------- decode (fp16 z gather) -------------------------------------
__global__ void k_decode(const int* __restrict__ pos, const int* __restrict__ neg,
                         float* __restrict__ out) {
    int gw = (blockIdx.x * blockDim.x + threadIdx.x) >> 5;
    if (gw >= 2 * EPP) return;
    int lane = threadIdx.x & 31;
    int a, b;
    if (gw < EPP) { a = pos[gw];        b = pos[EPP + gw]; }
    else          { int j = gw - EPP; a = neg[j]; b = neg[EPP + j]; }
    const __half2* Z = (const __half2*)g_z;
    float2 za = __half22float2(Z[(size_t)a * 32 + lane]);
    float2 zb = __half22float2(Z[(size_t)b * 32 + lane]);
    float p = za.x * zb.x + za.y * zb.y;
#pragma unroll
    for (int o = 16; o > 0; o >>= 1) p += __shfl_xor_sync(0xFFFFFFFFu, p, o);
    if (lane == 0) out[gw] = p;
}

// ---------------- launch ------------------------------------------------------
extern "C" void kernel_launch(void* const* d_in, const int* in_sizes, int n_in,
                              void* d_out, int out_size) {
    const float* x   = (const float*)d_in[0];
    const int*   ei  = (const int*)  d_in[1];
    const int*   pos = (const int*)  d_in[2];
    const int*   neg = (const int*)  d_in[3];
    const float* W1  = (const float*)d_in[4];
    const float* b1  = (const float*)d_in[5];
    const float* W2  = (const float*)d_in[6];
    const float* b2  = (const float*)d_in[7];
    float* out = (float*)d_out;

    const int* src = ei;
    const int* dst = ei + EE;
    const int nb_scan = (NN + 511) / 512;  // 196

    static cudaStream_t s2 = nullptr;
    static cudaEvent_t ev0 = nullptr, evD = nullptr, ev1 = nullptr;
    if (!s2) {
        cudaStreamCreateWithFlags(&s2, cudaStreamNonBlocking);
        cudaEventCreateWithFlags(&ev0, cudaEventDisableTiming);
        cudaEventCreateWithFlags(&evD, cudaEventDisableTiming);
        cudaEventCreateWithFlags(&ev1, cudaEventDisableTiming);
    }

    // fork at the very start: gemm1 path overlaps the CSR build
    cudaEventRecord(ev0, 0);
    cudaStreamWaitEvent(s2, ev0, 0);

    k_count<<<(EE + 255) / 256, 256>>>(dst);                    // #1 main
    k_wprep<<<48, 256, 0, s2>>>(W1, W2);                        // #2 s2
    k_scanA<<<nb_scan, 512>>>();                                // #3 main (scan+dinv)
    k_tc<1><<<(NN + 127) / 128, 256, 0, s2>>>(x, nullptr, 0);   // #4 s2 (profiled)
    cudaEventRecord(evD, 0);                                    // dinv ready

    k_scan2<<<1, 256>>>(nb_scan);                               // main
    k_scan3<<<nb_scan, 512>>>();                                // main
    k_fill<<<(EE + 255) / 256, 256>>>(src, dst);                // main

    // s2: prescale hs1 (needs dinv + tc1), reset deg for next call
    cudaStreamWaitEvent(s2, evD, 0);
    k_scale1<<<(NN * 32 + 255) / 256, 256, 0, s2>>>();          // s2
    k_reset<<<(NN + 255) / 256, 256, 0, s2>>>();                // s2 (after scanA via evD)
    cudaEventRecord(ev1, s2);

    // join: agg1 needs CSR (main, in-order) + prescaled hs1 (s2)
    cudaStreamWaitEvent(0, ev1, 0);

    k_agg1<<<(NN * 32 + 255) / 256, 256>>>();
    k_tc<2><<<(NN + 255) / 256, 256>>>(nullptr, b1, 0);
    k_agg2<<<(NN * 32 + 255) / 256, 256>>>(b2);
    k_decode<<<(2 * EPP * 32 + 255) / 256, 256>>>(pos, neg, out);
}

// round 9
// speedup vs baseline: 1.1624x; 1.0902x over previous
#include <cuda_runtime.h>
#include <cuda_fp16.h>
#include <cstdint>

#define NN 100000
#define EE 1600000
#define EPP 200000

// ---------------- scratch (static device globals; no allocation) ------------
// Zero-init at module load covers call #1; k_reset re-zeroes g_deg each call.
__device__ int      g_deg[NN];
__device__ int      g_off[NN + 1];
__device__ int      g_cur[NN];
__device__ int      g_adj[EE];
__device__ float    g_dinv[NN];
__device__ __half   g_hs1[(size_t)NN * 128]; // x@W1 -> prescaled by dinv[row]
__device__ __half   g_a1h[(size_t)NN * 128]; // aggregated layer-1 (fp16)
__device__ __half   g_hs2[(size_t)NN * 64];  // dinv[row]*relu(a1+b1)@W2 (fp16)
__device__ __half   g_z  [(size_t)NN * 64];  // final embeddings (fp16)
__device__ int      g_bsum[256];
// packed weights: [n][k2] half2 = (W[2k2][n], W[2k2+1][n])
__device__ unsigned g_W1p[128 * 64];
__device__ unsigned g_W2p[64 * 64];

// ---------------- fp16 helpers ----------------------------------------------
__device__ __forceinline__ unsigned f2h2(float a, float b) {
    __half2 h = __floats2half2_rn(a, b);
    return *reinterpret_cast<unsigned*>(&h);
}
__device__ __forceinline__ float2 h2f2(unsigned u) {
    __half2 h = *reinterpret_cast<__half2*>(&u);
    return __half22float2(h);
}
__device__ __forceinline__ unsigned hadd2u(unsigned a, unsigned b) {
    __half2 r = __hadd2(*reinterpret_cast<__half2*>(&a), *reinterpret_cast<__half2*>(&b));
    return *reinterpret_cast<unsigned*>(&r);
}

__device__ __forceinline__ void mmaf16(float* c, const unsigned* a, unsigned b0, unsigned b1) {
    asm("mma.sync.aligned.m16n8k16.row.col.f32.f16.f16.f32 "
        "{%0,%1,%2,%3}, {%4,%5,%6,%7}, {%8,%9}, {%0,%1,%2,%3};"
        : "+f"(c[0]), "+f"(c[1]), "+f"(c[2]), "+f"(c[3])
        : "r"(a[0]), "r"(a[1]), "r"(a[2]), "r"(a[3]), "r"(b0), "r"(b1));
}

__device__ __forceinline__ void ldsm4(unsigned* r, unsigned addr) {
    asm volatile("ldmatrix.sync.aligned.m8n8.x4.shared.b16 {%0,%1,%2,%3}, [%4];"
        : "=r"(r[0]), "=r"(r[1]), "=r"(r[2]), "=r"(r[3]) : "r"(addr));
}

// ---------------- degree / CSR build ----------------------------------------
__global__ void k_count(const int* __restrict__ dst) {
    int e = (blockIdx.x * blockDim.x + threadIdx.x) * 4;
    if (e < EE) {
        int4 d = *(const int4*)(dst + e);
        atomicAdd(&g_deg[d.x], 1);
        atomicAdd(&g_deg[d.y], 1);
        atomicAdd(&g_deg[d.z], 1);
        atomicAdd(&g_deg[d.w], 1);
    }
}

// fused: block scan of deg + dinv computation
__global__ void k_scanA() {
    __shared__ int s[512];
    int t = threadIdx.x;
    int idx = blockIdx.x * 512 + t;
    int v = (idx < NN) ? g_deg[idx] : 0;
    if (idx < NN) g_dinv[idx] = rsqrtf((float)(v + 1));  // +1 self loop
    s[t] = v;
    __syncthreads();
#pragma unroll
    for (int o = 1; o < 512; o <<= 1) {
        int x = (t >= o) ? s[t - o] : 0;
        __syncthreads();
        s[t] += x;
        __syncthreads();
    }
    if (idx < NN) g_off[idx] = s[t] - v;
    if (t == 511) g_bsum[blockIdx.x] = s[511];
}

// fused scan2+scan3: each block reduces its g_bsum prefix, then offsets
__global__ void k_scan3() {
    __shared__ int s[512];
    int t = threadIdx.x;
    s[t] = (t < (int)blockIdx.x) ? g_bsum[t] : 0;   // bid <= 195 < 512
    __syncthreads();
#pragma unroll
    for (int o = 256; o > 0; o >>= 1) {
        if (t < o) s[t] += s[t + o];
        __syncthreads();
    }
    int boff = s[0];
    int idx = blockIdx.x * 512 + t;
    if (idx < NN) {
        int val = g_off[idx] + boff;
        g_off[idx] = val;
        g_cur[idx] = val;
        if (idx == 0) g_off[NN] = EE;
    }
}

__global__ void k_fill(const int* __restrict__ src, const int* __restrict__ dst) {
    int e = (blockIdx.x * blockDim.x + threadIdx.x) * 4;
    if (e < EE) {
        int4 d = *(const int4*)(dst + e);
        int4 sv = *(const int4*)(src + e);
        g_adj[atomicAdd(&g_cur[d.x], 1)] = sv.x;
        g_adj[atomicAdd(&g_cur[d.y], 1)] = sv.y;
        g_adj[atomicAdd(&g_cur[d.z], 1)] = sv.z;
        g_adj[atomicAdd(&g_cur[d.w], 1)] = sv.w;
    }
}

// zero g_deg for the NEXT call (runs on s2, off critical path)
__global__ void k_reset() {
    int i = blockIdx.x * blockDim.x + threadIdx.x;
    if (i < NN) g_deg[i] = 0;
}

// ---------------- weight fp16 transpose-pack ---------------------------------
__global__ void k_wprep(const float* __restrict__ W1, const float* __restrict__ W2) {
    int i = blockIdx.x * blockDim.x + threadIdx.x;
    if (i < 128 * 64) {
        int n = i >> 6, k2 = i & 63;
        g_W1p[i] = f2h2(W1[(2 * k2) * 128 + n], W1[(2 * k2 + 1) * 128 + n]);
    } else if (i < 128 * 64 + 64 * 64) {
        int j = i - 128 * 64;
        int n = j >> 6, k2 = j & 63;
        g_W2p[j] = f2h2(W2[(2 * k2) * 64 + n], W2[(2 * k2 + 1) * 64 + n]);
    }
}

// ---------------- in-place prescale: hs1[r] *= dinv[r] -----------------------
__global__ void k_scale1() {
    int idx = blockIdx.x * blockDim.x + threadIdx.x;   // NN*32 lane-slots
    int gw = idx >> 5, lane = idx & 31;
    if (gw >= NN) return;
    float dd = g_dinv[gw];
    uint2* p = (uint2*)g_hs1 + (size_t)gw * 32 + lane;
    uint2 v = *p;
    float2 q0 = h2f2(v.x), q1 = h2f2(v.y);
    v.x = f2h2(q0.x * dd, q0.y * dd);
    v.y = f2h2(q1.x * dd, q1.y * dd);
    *p = v;
}

// ---------------- tensor-core GEMM, pure fp16, ldmatrix frags ----------------
// LAYER 1: hs1[NN,128] = fp16(x) @ fp16(W1), MT=128, NOUT=128
// LAYER 2: hs2[NN,64]  = dinv[r]*relu(a1h+b1) @ fp16(W2), MT=256, NOUT=64
template<int LAYER>
__global__ __launch_bounds__(256) void k_tc(const float* __restrict__ Xsrc,
                                            const float* __restrict__ bias,
                                            int rowbase) {
    constexpr int MT   = (LAYER == 1) ? 128 : 256;
    constexpr int NOUT = (LAYER == 1) ? 128 : 64;

    const unsigned* Wp  = (LAYER == 1) ? g_W1p : g_W2p;
    __half*         Out = (LAYER == 1) ? g_hs1 : g_hs2;

    __shared__ unsigned Ah[MT * 12];
    __shared__ unsigned Bh[NOUT * 12];

    const int tid  = threadIdx.x;
    const int lane = tid & 31;
    const int wid  = tid >> 5;
    const int g    = lane >> 2;
    const int t4   = lane & 3;
    const int row0 = rowbase + blockIdx.x * MT;
    const int warpM = (LAYER == 1) ? (wid >> 1) * 32 : wid * 32;
    const int n0    = (LAYER == 1) ? (wid & 1) * 64 : 0;

    const unsigned sAh = (unsigned)__cvta_generic_to_shared(Ah);
    const unsigned sBh = (unsigned)__cvta_generic_to_shared(Bh);
    const int l7 = lane & 7;
    const int r8 = (lane >> 3) & 1;
    const int w4 = (lane >> 4) * 4;
    unsigned aAddr[2];
#pragma unroll
    for (int mi = 0; mi < 2; mi++) {
        int row = warpM + mi * 16 + l7 + r8 * 8;
        aAddr[mi] = sAh + (unsigned)((row * 12 + w4) * 4);
    }
    unsigned bAddr[4];
    const int bw4 = ((lane >> 3) & 1) * 4;
    const int bn8 = (lane >= 16) ? 8 : 0;
#pragma unroll
    for (int nn = 0; nn < 4; nn++) {
        int nrow = n0 + nn * 16 + l7 + bn8;
        bAddr[nn] = sBh + (unsigned)((nrow * 12 + bw4) * 4);
    }

    float acc[2][8][4];
#pragma unroll
    for (int mi = 0; mi < 2; mi++)
#pragma unroll
        for (int ni = 0; ni < 8; ni++)
#pragma unroll
            for (int q = 0; q < 4; q++) acc[mi][ni][q] = 0.f;

#pragma unroll 1
    for (int kc = 0; kc < 8; kc++) {
        const int kbase = kc * 16;
        if (LAYER == 1) {
#pragma unroll
            for (int j = 0; j < MT / 64; j++) {
                int idx = tid + 256 * j;
                int r = idx >> 2, c4 = idx & 3;
                int gr = row0 + r;
                float4 v = {0.f, 0.f, 0.f, 0.f};
                if (gr < NN)
                    v = ((const float4*)(Xsrc + (size_t)gr * 128 + kbase))[c4];
                *(uint2*)&Ah[r * 12 + c4 * 2] =
                    make_uint2(f2h2(v.x, v.y), f2h2(v.z, v.w));
            }
        } else {
            int r = tid;
            int gr = row0 + r;
            uint4 u0 = {0,0,0,0}, u1 = {0,0,0,0};
            if (gr < NN) {
                const uint4* p = (const uint4*)(g_a1h + (size_t)gr * 128 + kbase);
                u0 = p[0]; u1 = p[1];
                const float2* bp = (const float2*)(bias + kbase);
                unsigned* uw = &u0.x;
#pragma unroll
                for (int w = 0; w < 4; w++) {
                    float2 f = h2f2(uw[w]); float2 b = bp[w];
                    uw[w] = f2h2(fmaxf(f.x + b.x, 0.f), fmaxf(f.y + b.y, 0.f));
                }
                unsigned* uw1 = &u1.x;
#pragma unroll
                for (int w = 0; w < 4; w++) {
                    float2 f = h2f2(uw1[w]); float2 b = bp[w + 4];
                    uw1[w] = f2h2(fmaxf(f.x + b.x, 0.f), fmaxf(f.y + b.y, 0.f));
                }
            }
            *(uint4*)&Ah[r * 12]     = u0;
            *(uint4*)&Ah[r * 12 + 4] = u1;
        }
#pragma unroll
        for (int j = 0; j < NOUT / 64; j++) {
            int idx = tid + 256 * j;
            int n = idx >> 2, jp = (idx & 3) * 2;
            *(uint2*)&Bh[n * 12 + jp] = *(const uint2*)&Wp[n * 64 + kc * 8 + jp];
        }
        __syncthreads();

        unsigned ah[2][4];
#pragma unroll
        for (int mi = 0; mi < 2; mi++) ldsm4(ah[mi], aAddr[mi]);
#pragma unroll
        for (int nn = 0; nn < 4; nn++) {
            unsigned bh[4];
            ldsm4(bh, bAddr[nn]);
#pragma unroll
            for (int p = 0; p < 2; p++) {
                int ni = nn * 2 + p;
#pragma unroll
                for (int mi = 0; mi < 2; mi++)
                    mmaf16(acc[mi][ni], ah[mi], bh[p * 2], bh[p * 2 + 1]);
            }
        }
        __syncthreads();
    }

    // epilogue: fp16 output; LAYER 2 prescales by dinv[row]
#pragma unroll
    for (int mi = 0; mi < 2; mi++) {
#pragma unroll
        for (int ni = 0; ni < 8; ni++) {
            int r  = row0 + warpM + mi * 16 + g;
            int cc = n0 + ni * 8 + 2 * t4;
            if (r < NN) {
                float s = (LAYER == 2) ? g_dinv[r] : 1.f;
                __half2 o = __floats2half2_rn(acc[mi][ni][0] * s, acc[mi][ni][1] * s);
                *((__half2*)(Out + (size_t)r * NOUT + cc)) = o;
            }
            if (r + 8 < NN) {
                float s = (LAYER == 2) ? g_dinv[r + 8] : 1.f;
                __half2 o = __floats2half2_rn(acc[mi][ni][2] * s, acc[mi][ni][3] * s);
                *((__half2*)(Out + (size_t)(r + 8) * NOUT + cc)) = o;
            }
        }
    }
}

// ---------------- AGG 1: a1h[d] = dd * sum of prescaled rows -----------------
// 8-edge batches, fp16 pairwise-tree (HADD2) then fp32 merge.
__global__ void k_agg1() {
    int gw = (blockIdx.x * blockDim.x + threadIdx.x) >> 5;
    if (gw >= NN) return;
    int lane = threadIdx.x & 31;
    int o0 = g_off[gw], o1 = g_off[gw + 1];
    const uint2* base = (const uint2*)g_hs1;
    float dd = g_dinv[gw];

    uint2 sv = base[(size_t)gw * 32 + lane];
    float2 p0 = h2f2(sv.x), p1 = h2f2(sv.y);
    float a0 = p0.x, a1 = p0.y, a2 = p1.x, a3 = p1.y;

    int i = o0;
    for (; i + 8 <= o1; i += 8) {
        int s0 = g_adj[i],     s1 = g_adj[i + 1], s2 = g_adj[i + 2], s3 = g_adj[i + 3];
        int s4 = g_adj[i + 4], s5 = g_adj[i + 5], s6 = g_adj[i + 6], s7 = g_adj[i + 7];
        uint2 v0 = base[(size_t)s0 * 32 + lane];
        uint2 v1 = base[(size_t)s1 * 32 + lane];
        uint2 v2 = base[(size_t)s2 * 32 + lane];
        uint2 v3 = base[(size_t)s3 * 32 + lane];
        uint2 v4 = base[(size_t)s4 * 32 + lane];
        uint2 v5 = base[(size_t)s5 * 32 + lane];
        uint2 v6 = base[(size_t)s6 * 32 + lane];
        uint2 v7 = base[(size_t)s7 * 32 + lane];
        unsigned tx = hadd2u(hadd2u(hadd2u(v0.x, v1.x), hadd2u(v2.x, v3.x)),
                             hadd2u(hadd2u(v4.x, v5.x), hadd2u(v6.x, v7.x)));
        unsigned ty = hadd2u(hadd2u(hadd2u(v0.y, v1.y), hadd2u(v2.y, v3.y)),
                             hadd2u(hadd2u(v4.y, v5.y), hadd2u(v6.y, v7.y)));
        float2 qx = h2f2(tx), qy = h2f2(ty);
        a0 += qx.x; a1 += qx.y; a2 += qy.x; a3 += qy.y;
    }
    for (; i < o1; i++) {
        int s = g_adj[i];
        uint2 v = base[(size_t)s * 32 + lane];
        float2 q0 = h2f2(v.x), q1 = h2f2(v.y);
        a0 += q0.x; a1 += q0.y; a2 += q1.x; a3 += q1.y;
    }
    uint2 o;
    o.x = f2h2(a0 * dd, a1 * dd);
    o.y = f2h2(a2 * dd, a3 * dd);
    ((uint2*)g_a1h)[(size_t)gw * 32 + lane] = o;
}

// ---------------- AGG 2: z[d] = dd * sum of prescaled hs2 rows + b2 ----------
__global__ void k_agg2(const float* __restrict__ b2) {
    int gw = (blockIdx.x * blockDim.x + threadIdx.x) >> 5;
    if (gw >= NN) return;
    int lane = threadIdx.x & 31;
    int o0 = g_off[gw], o1 = g_off[gw + 1];
    const unsigned* base = (const unsigned*)g_hs2;
    float dd = g_dinv[gw];

    float2 p = h2f2(base[(size_t)gw * 32 + lane]);
    float a0 = p.x, a1 = p.y;

    int i = o0;
    for (; i + 8 <= o1; i += 8) {
        int s0 = g_adj[i],     s1 = g_adj[i + 1], s2 = g_adj[i + 2], s3 = g_adj[i + 3];
        int s4 = g_adj[i + 4], s5 = g_adj[i + 5], s6 = g_adj[i + 6], s7 = g_adj[i + 7];
        unsigned v0 = base[(size_t)s0 * 32 + lane];
        unsigned v1 = base[(size_t)s1 * 32 + lane];
        unsigned v2 = base[(size_t)s2 * 32 + lane];
        unsigned v3 = base[(size_t)s3 * 32 + lane];
        unsigned v4 = base[(size_t)s4 * 32 + lane];
        unsigned v5 = base[(size_t)s5 * 32 + lane];
        unsigned v6 = base[(size_t)s6 * 32 + lane];
        unsigned v7 = base[(size_t)s7 * 32 + lane];
        unsigned t = hadd2u(hadd2u(hadd2u(v0, v1), hadd2u(v2, v3)),
                            hadd2u(hadd2u(v4, v5), hadd2u(v6, v7)));
        float2 q = h2f2(t);
        a0 += q.x; a1 += q.y;
    }
    for (; i < o1; i++) {
        float2 v = h2f2(base[(size_t)g_adj[i] * 32 + lane]);
        a0 += v.x; a1 += v.y;
    }
    float2 b = ((const float2*)b2)[lane];
    __half2 oz = __floats2half2_rn(a0 * dd + b.x, a1 * dd + b.y);
    ((__half2*)g_z)[(size_t)gw * 32 + lane] = oz;
}

// ---------------- decode (fp16 z gather) -------------------------------------
__global__ void k_decode(const int* __restrict__ pos, const int* __restrict__ neg,
                         float* __restrict__ out) {
    int gw = (blockIdx.x * blockDim.x + threadIdx.x) >> 5;
    if (gw >= 2 * EPP) return;
    int lane = threadIdx.x & 31;
    int a, b;
    if (gw < EPP) { a = pos[gw];        b = pos[EPP + gw]; }
    else          { int j = gw - EPP; a = neg[j]; b = neg[EPP + j]; }
    const __half2* Z = (const __half2*)g_z;
    float2 za = __half22float2(Z[(size_t)a * 32 + lane]);
    float2 zb = __half22float2(Z[(size_t)b * 32 + lane]);
    float p = za.x * zb.x + za.y * zb.y;
#pragma unroll
    for (int o = 16; o > 0; o >>= 1) p += __shfl_xor_sync(0xFFFFFFFFu, p, o);
    if (lane == 0) out[gw] = p;
}

// ---------------- launch ------------------------------------------------------
extern "C" void kernel_launch(void* const* d_in, const int* in_sizes, int n_in,
                              void* d_out, int out_size) {
    const float* x   = (const float*)d_in[0];
    const int*   ei  = (const int*)  d_in[1];
    const int*   pos = (const int*)  d_in[2];
    const int*   neg = (const int*)  d_in[3];
    const float* W1  = (const float*)d_in[4];
    const float* b1  = (const float*)d_in[5];
    const float* W2  = (const float*)d_in[6];
    const float* b2  = (const float*)d_in[7];
    float* out = (float*)d_out;

    const int* src = ei;
    const int* dst = ei + EE;
    const int nb_scan = (NN + 511) / 512;  // 196

    static cudaStream_t s2 = nullptr;
    static cudaEvent_t ev0 = nullptr, evD = nullptr, ev1 = nullptr;
    if (!s2) {
        cudaStreamCreateWithFlags(&s2, cudaStreamNonBlocking);
        cudaEventCreateWithFlags(&ev0, cudaEventDisableTiming);
        cudaEventCreateWithFlags(&evD, cudaEventDisableTiming);
        cudaEventCreateWithFlags(&ev1, cudaEventDisableTiming);
    }

    // fork at the very start: gemm1 path overlaps the CSR build
    cudaEventRecord(ev0, 0);
    cudaStreamWaitEvent(s2, ev0, 0);

    k_count<<<(EE / 4 + 255) / 256, 256>>>(dst);                // #1 main
    k_wprep<<<48, 256, 0, s2>>>(W1, W2);                        // #2 s2
    k_scanA<<<nb_scan, 512>>>();                                // #3 main (scan+dinv)
    k_tc<1><<<(NN + 127) / 128, 256, 0, s2>>>(x, nullptr, 0);   // #4 s2 (profiled)
    cudaEventRecord(evD, 0);                                    // dinv ready

    k_scan3<<<nb_scan, 512>>>();                                // main (fused scan2+3)
    k_fill<<<(EE / 4 + 255) / 256, 256>>>(src, dst);            // main

    // s2: prescale hs1 (needs dinv + tc1), reset deg for next call
    cudaStreamWaitEvent(s2, evD, 0);
    k_scale1<<<(NN * 32 + 255) / 256, 256, 0, s2>>>();          // s2
    k_reset<<<(NN + 255) / 256, 256, 0, s2>>>();                // s2 (after scanA via evD)
    cudaEventRecord(ev1, s2);

    // join: agg1 needs CSR (main, in-order) + prescaled hs1 (s2)
    cudaStreamWaitEvent(0, ev1, 0);

    k_agg1<<<(NN * 32 + 255) / 256, 256>>>();
    k_tc<2><<<(NN + 255) / 256, 256>>>(nullptr, b1, 0);
    k_agg2<<<(NN * 32 + 255) / 256, 256>>>(b2);
    k_decode<<<(2 * EPP * 32 + 255) / 256, 256>>>(pos, neg, out);
}

// round 11
// speedup vs baseline: 1.4129x; 1.2155x over previous
#include <cuda_runtime.h>
#include <cuda_fp16.h>
#include <cstdint>

#define NN 100000
#define EE 1600000
#define EPP 200000

// ---------------- scratch (static device globals; no allocation) ------------
// Zero-init at module load covers call #1; k_reset re-zeroes g_deg each call.
__device__ int      g_deg[NN];
__device__ int      g_off[NN + 1];
__device__ int      g_cur[NN];
__device__ int      g_adj[EE];
__device__ float    g_dinv[NN];
__device__ __half   g_hs1[(size_t)NN * 128]; // dinv[r]*(x@W1)  (fp16)
__device__ __half   g_a1h[(size_t)NN * 128]; // aggregated layer-1 (fp16)
__device__ __half   g_hs2[(size_t)NN * 64];  // dinv[r]*relu(a1+b1)@W2 (fp16)
__device__ __half   g_z  [(size_t)NN * 64];  // final embeddings (fp16)
__device__ int      g_bsum[256];
// packed weights: [n][k2] half2 = (W[2k2][n], W[2k2+1][n])
__device__ unsigned g_W1p[128 * 64];
__device__ unsigned g_W2p[64 * 64];

// ---------------- fp16 helpers ----------------------------------------------
__device__ __forceinline__ unsigned f2h2(float a, float b) {
    __half2 h = __floats2half2_rn(a, b);
    return *reinterpret_cast<unsigned*>(&h);
}
__device__ __forceinline__ float2 h2f2(unsigned u) {
    __half2 h = *reinterpret_cast<__half2*>(&u);
    return __half22float2(h);
}
__device__ __forceinline__ unsigned hadd2u(unsigned a, unsigned b) {
    __half2 r = __hadd2(*reinterpret_cast<__half2*>(&a), *reinterpret_cast<__half2*>(&b));
    return *reinterpret_cast<unsigned*>(&r);
}

__device__ __forceinline__ void mmaf16(float* c, const unsigned* a, unsigned b0, unsigned b1) {
    asm("mma.sync.aligned.m16n8k16.row.col.f32.f16.f16.f32 "
        "{%0,%1,%2,%3}, {%4,%5,%6,%7}, {%8,%9}, {%0,%1,%2,%3};"
        : "+f"(c[0]), "+f"(c[1]), "+f"(c[2]), "+f"(c[3])
        : "r"(a[0]), "r"(a[1]), "r"(a[2]), "r"(a[3]), "r"(b0), "r"(b1));
}

__device__ __forceinline__ void ldsm4(unsigned* r, unsigned addr) {
    asm volatile("ldmatrix.sync.aligned.m8n8.x4.shared.b16 {%0,%1,%2,%3}, [%4];"
        : "=r"(r[0]), "=r"(r[1]), "=r"(r[2]), "=r"(r[3]) : "r"(addr));
}

// ---------------- degree / CSR build ----------------------------------------
__global__ void k_count(const int* __restrict__ dst) {
    int e = (blockIdx.x * blockDim.x + threadIdx.x) * 4;
    if (e < EE) {
        int4 d = *(const int4*)(dst + e);
        atomicAdd(&g_deg[d.x], 1);
        atomicAdd(&g_deg[d.y], 1);
        atomicAdd(&g_deg[d.z], 1);
        atomicAdd(&g_deg[d.w], 1);
    }
}

// fused: block scan of deg + dinv computation
__global__ void k_scanA() {
    __shared__ int s[512];
    int t = threadIdx.x;
    int idx = blockIdx.x * 512 + t;
    int v = (idx < NN) ? g_deg[idx] : 0;
    if (idx < NN) g_dinv[idx] = rsqrtf((float)(v + 1));  // +1 self loop
    s[t] = v;
    __syncthreads();
#pragma unroll
    for (int o = 1; o < 512; o <<= 1) {
        int x = (t >= o) ? s[t - o] : 0;
        __syncthreads();
        s[t] += x;
        __syncthreads();
    }
    if (idx < NN) g_off[idx] = s[t] - v;
    if (t == 511) g_bsum[blockIdx.x] = s[511];
}

// fused scan2+scan3: each block reduces its g_bsum prefix, then offsets
__global__ void k_scan3() {
    __shared__ int s[512];
    int t = threadIdx.x;
    s[t] = (t < (int)blockIdx.x) ? g_bsum[t] : 0;   // bid <= 195 < 512
    __syncthreads();
#pragma unroll
    for (int o = 256; o > 0; o >>= 1) {
        if (t < o) s[t] += s[t + o];
        __syncthreads();
    }
    int boff = s[0];
    int idx = blockIdx.x * 512 + t;
    if (idx < NN) {
        int val = g_off[idx] + boff;
        g_off[idx] = val;
        g_cur[idx] = val;
        if (idx == 0) g_off[NN] = EE;
    }
}

__global__ void k_fill(const int* __restrict__ src, const int* __restrict__ dst) {
    int e = (blockIdx.x * blockDim.x + threadIdx.x) * 4;
    if (e < EE) {
        int4 d = *(const int4*)(dst + e);
        int4 sv = *(const int4*)(src + e);
        g_adj[atomicAdd(&g_cur[d.x], 1)] = sv.x;
        g_adj[atomicAdd(&g_cur[d.y], 1)] = sv.y;
        g_adj[atomicAdd(&g_cur[d.z], 1)] = sv.z;
        g_adj[atomicAdd(&g_cur[d.w], 1)] = sv.w;
    }
}

// zero g_deg for the NEXT call (runs on s2 after scanA, off critical path)
__global__ void k_reset() {
    int i = blockIdx.x * blockDim.x + threadIdx.x;
    if (i < NN) g_deg[i] = 0;
}

// ---------------- weight fp16 transpose-pack ---------------------------------
__global__ void k_wprep(const float* __restrict__ W1, const float* __restrict__ W2) {
    int i = blockIdx.x * blockDim.x + threadIdx.x;
    if (i < 128 * 64) {
        int n = i >> 6, k2 = i & 63;
        g_W1p[i] = f2h2(W1[(2 * k2) * 128 + n], W1[(2 * k2 + 1) * 128 + n]);
    } else if (i < 128 * 64 + 64 * 64) {
        int j = i - 128 * 64;
        int n = j >> 6, k2 = j & 63;
        g_W2p[j] = f2h2(W2[(2 * k2) * 64 + n], W2[(2 * k2 + 1) * 64 + n]);
    }
}

// ---------------- tensor-core GEMM, 2 K-stages, dinv epilogue ----------------
// LAYER 1: hs1[NN,128] = dinv[r] * (fp16(x) @ fp16(W1)),          NOUT=128
// LAYER 2: hs2[NN,64]  = dinv[r] * (relu(a1h+b1) @ fp16(W2)),     NOUT=64
// MT=128 rows/block, 256 threads = 8 warps.
// K=128 handled in 2 stages of 64 halfs (32 half2 words), row stride 36 words.
template<int LAYER>
__global__ __launch_bounds__(256) void k_tc(const float* __restrict__ Xsrc,
                                            const float* __restrict__ bias) {
    constexpr int NOUT = (LAYER == 1) ? 128 : 64;
    constexpr int NMT  = (LAYER == 1) ? 2 : 1;
    constexpr int ST   = 36;

    const unsigned* Wp  = (LAYER == 1) ? g_W1p : g_W2p;
    __half*         Out = (LAYER == 1) ? g_hs1 : g_hs2;

    __shared__ unsigned Ah[128 * ST];
    __shared__ unsigned Bh[NOUT * ST];

    const int tid  = threadIdx.x;
    const int lane = tid & 31;
    const int wid  = tid >> 5;
    const int g    = lane >> 2;
    const int t4   = lane & 3;
    const int row0 = blockIdx.x * 128;
    const int warpM = (LAYER == 1) ? (wid >> 1) * 32 : wid * 16;
    const int n0    = (LAYER == 1) ? (wid & 1) * 64 : 0;

    const unsigned sAh = (unsigned)__cvta_generic_to_shared(Ah);
    const unsigned sBh = (unsigned)__cvta_generic_to_shared(Bh);
    const int l7 = lane & 7;
    const int r8 = (lane >> 3) & 1;
    const int w4 = (lane >> 4) * 4;
    unsigned aAddr[NMT];
#pragma unroll
    for (int mi = 0; mi < NMT; mi++) {
        int row = warpM + mi * 16 + l7 + r8 * 8;
        aAddr[mi] = sAh + (unsigned)((row * ST + w4) * 4);
    }
    unsigned bAddr[4];
    const int bw4 = ((lane >> 3) & 1) * 4;
    const int bn8 = (lane >= 16) ? 8 : 0;
#pragma unroll
    for (int nn = 0; nn < 4; nn++) {
        int nrow = n0 + nn * 16 + l7 + bn8;
        bAddr[nn] = sBh + (unsigned)((nrow * ST + bw4) * 4);
    }

    float acc[NMT][8][4];
#pragma unroll
    for (int mi = 0; mi < NMT; mi++)
#pragma unroll
        for (int ni = 0; ni < 8; ni++)
#pragma unroll
            for (int q = 0; q < 4; q++) acc[mi][ni][q] = 0.f;

#pragma unroll 1
    for (int ko = 0; ko < 2; ko++) {
        // ---- stage A chunk: 128 rows x 32 words --------------------------
        if (LAYER == 1) {
#pragma unroll
            for (int j = 0; j < 8; j++) {
                int idx = tid + 256 * j;        // 0..2047 float4 slots
                int r = idx >> 4, c4 = idx & 15;
                int gr = row0 + r;
                float4 v = {0.f, 0.f, 0.f, 0.f};
                if (gr < NN)
                    v = ((const float4*)(Xsrc + (size_t)gr * 128 + ko * 64))[c4];
                *(uint2*)&Ah[r * ST + c4 * 2] =
                    make_uint2(f2h2(v.x, v.y), f2h2(v.z, v.w));
            }
        } else {
#pragma unroll
            for (int j = 0; j < 8; j++) {
                int idx = tid + 256 * j;        // 0..2047 uint2 slots
                int r = idx >> 4, u2 = idx & 15;
                int gr = row0 + r;
                uint2 u = {0, 0};
                if (gr < NN) {
                    u = ((const uint2*)(g_a1h + (size_t)gr * 128))[ko * 16 + u2];
                    float2 ba = ((const float2*)bias)[ko * 32 + u2 * 2];
                    float2 bb = ((const float2*)bias)[ko * 32 + u2 * 2 + 1];
                    float2 f0 = h2f2(u.x), f1 = h2f2(u.y);
                    u.x = f2h2(fmaxf(f0.x + ba.x, 0.f), fmaxf(f0.y + ba.y, 0.f));
                    u.y = f2h2(fmaxf(f1.x + bb.x, 0.f), fmaxf(f1.y + bb.y, 0.f));
                }
                *(uint2*)&Ah[r * ST + u2 * 2] = u;
            }
        }
        // ---- stage B chunk: NOUT rows x 32 words -------------------------
#pragma unroll
        for (int j = 0; j < NOUT / 16; j++) {
            int idx = tid + 256 * j;            // uint2 slots
            int n = idx >> 4, u2 = idx & 15;
            *(uint2*)&Bh[n * ST + u2 * 2] =
                *(const uint2*)&Wp[n * 64 + ko * 32 + u2 * 2];
        }
        __syncthreads();

        // ---- 4 k16 rounds -------------------------------------------------
#pragma unroll
        for (int kc = 0; kc < 4; kc++) {
            const unsigned koff = kc * 32;      // 8 words = 32 bytes
            unsigned ah[NMT][4];
#pragma unroll
            for (int mi = 0; mi < NMT; mi++) ldsm4(ah[mi], aAddr[mi] + koff);
#pragma unroll
            for (int nn = 0; nn < 4; nn++) {
                unsigned bh[4];
                ldsm4(bh, bAddr[nn] + koff);
#pragma unroll
                for (int p = 0; p < 2; p++) {
                    int ni = nn * 2 + p;
#pragma unroll
                    for (int mi = 0; mi < NMT; mi++)
                        mmaf16(acc[mi][ni], ah[mi], bh[p * 2], bh[p * 2 + 1]);
                }
            }
        }
        __syncthreads();
    }

    // ---- epilogue: dinv[r] prescale, fp16 output -------------------------
#pragma unroll
    for (int mi = 0; mi < NMT; mi++) {
#pragma unroll
        for (int ni = 0; ni < 8; ni++) {
            int r  = row0 + warpM + mi * 16 + g;
            int cc = n0 + ni * 8 + 2 * t4;
            if (r < NN) {
                float s = g_dinv[r];
                __half2 o = __floats2half2_rn(acc[mi][ni][0] * s, acc[mi][ni][1] * s);
                *((__half2*)(Out + (size_t)r * NOUT + cc)) = o;
            }
            if (r + 8 < NN) {
                float s = g_dinv[r + 8];
                __half2 o = __floats2half2_rn(acc[mi][ni][2] * s, acc[mi][ni][3] * s);
                *((__half2*)(Out + (size_t)(r + 8) * NOUT + cc)) = o;
            }
        }
    }
}

// ---------------- AGG 1: a1h[d] = dd * sum of prescaled rows -----------------
// 8-edge batches, fp16 pairwise-tree (HADD2) then fp32 merge.
__global__ void k_agg1() {
    int gw = (blockIdx.x * blockDim.x + threadIdx.x) >> 5;
    if (gw >= NN) return;
    int lane = threadIdx.x & 31;
    int o0 = g_off[gw], o1 = g_off[gw + 1];
    const uint2* base = (const uint2*)g_hs1;
    float dd = g_dinv[gw];

    uint2 sv = base[(size_t)gw * 32 + lane];
    float2 p0 = h2f2(sv.x), p1 = h2f2(sv.y);
    float a0 = p0.x, a1 = p0.y, a2 = p1.x, a3 = p1.y;

    int i = o0;
    for (; i + 8 <= o1; i += 8) {
        int s0 = g_adj[i],     s1 = g_adj[i + 1], s2 = g_adj[i + 2], s3 = g_adj[i + 3];
        int s4 = g_adj[i + 4], s5 = g_adj[i + 5], s6 = g_adj[i + 6], s7 = g_adj[i + 7];
        uint2 v0 = base[(size_t)s0 * 32 + lane];
        uint2 v1 = base[(size_t)s1 * 32 + lane];
        uint2 v2 = base[(size_t)s2 * 32 + lane];
        uint2 v3 = base[(size_t)s3 * 32 + lane];
        uint2 v4 = base[(size_t)s4 * 32 + lane];
        uint2 v5 = base[(size_t)s5 * 32 + lane];
        uint2 v6 = base[(size_t)s6 * 32 + lane];
        uint2 v7 = base[(size_t)s7 * 32 + lane];
        unsigned tx = hadd2u(hadd2u(hadd2u(v0.x, v1.x), hadd2u(v2.x, v3.x)),
                             hadd2u(hadd2u(v4.x, v5.x), hadd2u(v6.x, v7.x)));
        unsigned ty = hadd2u(hadd2u(hadd2u(v0.y, v1.y), hadd2u(v2.y, v3.y)),
                             hadd2u(hadd2u(v4.y, v5.y), hadd2u(v6.y, v7.y)));
        float2 qx = h2f2(tx), qy = h2f2(ty);
        a0 += qx.x; a1 += qx.y; a2 += qy.x; a3 += qy.y;
    }
    for (; i < o1; i++) {
        int s = g_adj[i];
        uint2 v = base[(size_t)s * 32 + lane];
        float2 q0 = h2f2(v.x), q1 = h2f2(v.y);
        a0 += q0.x; a1 += q0.y; a2 += q1.x; a3 += q1.y;
    }
    uint2 o;
    o.x = f2h2(a0 * dd, a1 * dd);
    o.y = f2h2(a2 * dd, a3 * dd);
    ((uint2*)g_a1h)[(size_t)gw * 32 + lane] = o;
}

// ---------------- AGG 2: z[d] = dd * sum of prescaled hs2 rows + b2 ----------
__global__ void k_agg2(const float* __restrict__ b2) {
    int gw = (blockIdx.x * blockDim.x + threadIdx.x) >> 5;
    if (gw >= NN) return;
    int lane = threadIdx.x & 31;
    int o0 = g_off[gw], o1 = g_off[gw + 1];
    const unsigned* base = (const unsigned*)g_hs2;
    float dd = g_dinv[gw];

    float2 p = h2f2(base[(size_t)gw * 32 + lane]);
    float a0 = p.x, a1 = p.y;

    int i = o0;
    for (; i + 8 <= o1; i += 8) {
        int s0 = g_adj[i],     s1 = g_adj[i + 1], s2 = g_adj[i + 2], s3 = g_adj[i + 3];
        int s4 = g_adj[i + 4], s5 = g_adj[i + 5], s6 = g_adj[i + 6], s7 = g_adj[i + 7];
        unsigned v0 = base[(size_t)s0 * 32 + lane];
        unsigned v1 = base[(size_t)s1 * 32 + lane];
        unsigned v2 = base[(size_t)s2 * 32 + lane];
        unsigned v3 = base[(size_t)s3 * 32 + lane];
        unsigned v4 = base[(size_t)s4 * 32 + lane];
        unsigned v5 = base[(size_t)s5 * 32 + lane];
        unsigned v6 = base[(size_t)s6 * 32 + lane];
        unsigned v7 = base[(size_t)s7 * 32 + lane];
        unsigned t = hadd2u(hadd2u(hadd2u(v0, v1), hadd2u(v2, v3)),
                            hadd2u(hadd2u(v4, v5), hadd2u(v6, v7)));
        float2 q = h2f2(t);
        a0 += q.x; a1 += q.y;
    }
    for (; i < o1; i++) {
        float2 v = h2f2(base[(size_t)g_adj[i] * 32 + lane]);
        a0 += v.x; a1 += v.y;
    }
    float2 b = ((const float2*)b2)[lane];
    __half2 oz = __floats2half2_rn(a0 * dd + b.x, a1 * dd + b.y);
    ((__half2*)g_z)[(size_t)gw * 32 + lane] = oz;
}

// ---------------- decode: 2 edges per warp (fp16 z gather) -------------------
__global__ void k_decode(const int* __restrict__ pos, const int* __restrict__ neg,
                         float* __restrict__ out) {
    int w = (blockIdx.x * blockDim.x + threadIdx.x) >> 5;
    int e0 = w * 2;
    if (e0 >= 2 * EPP) return;                 // e0 even => e0+1 < 2*EPP too
    int lane = threadIdx.x & 31;
    int a0, b0, a1, b1;
    {
        int e = e0;
        if (e < EPP) { a0 = pos[e]; b0 = pos[EPP + e]; }
        else         { a0 = neg[e - EPP]; b0 = neg[e]; }   // neg[EPP + (e-EPP)]
        e = e0 + 1;
        if (e < EPP) { a1 = pos[e]; b1 = pos[EPP + e]; }
        else         { a1 = neg[e - EPP]; b1 = neg[e]; }
    }
    const unsigned* Z = (const unsigned*)g_z;
    unsigned za0 = Z[(size_t)a0 * 32 + lane];
    unsigned zb0 = Z[(size_t)b0 * 32 + lane];
    unsigned za1 = Z[(size_t)a1 * 32 + lane];
    unsigned zb1 = Z[(size_t)b1 * 32 + lane];
    float2 xa0 = h2f2(za0), xb0 = h2f2(zb0);
    float2 xa1 = h2f2(za1), xb1 = h2f2(zb1);
    float p0 = xa0.x * xb0.x + xa0.y * xb0.y;
    float p1 = xa1.x * xb1.x + xa1.y * xb1.y;
#pragma unroll
    for (int o = 16; o > 0; o >>= 1) {
        p0 += __shfl_xor_sync(0xFFFFFFFFu, p0, o);
        p1 += __shfl_xor_sync(0xFFFFFFFFu, p1, o);
    }
    if (lane == 0) { out[e0] = p0; out[e0 + 1] = p1; }
}

// ---------------- launch ------------------------------------------------------
extern "C" void kernel_launch(void* const* d_in, const int* in_sizes, int n_in,
                              void* d_out, int out_size) {
    const float* x   = (const float*)d_in[0];
    const int*   ei  = (const int*)  d_in[1];
    const int*   pos = (const int*)  d_in[2];
    const int*   neg = (const int*)  d_in[3];
    const float* W1  = (const float*)d_in[4];
    const float* b1  = (const float*)d_in[5];
    const float* W2  = (const float*)d_in[6];
    const float* b2  = (const float*)d_in[7];
    float* out = (float*)d_out;

    const int* src = ei;
    const int* dst = ei + EE;
    const int nb_scan = (NN + 511) / 512;  // 196

    static cudaStream_t s2 = nullptr;
    static cudaEvent_t ev0 = nullptr, evD = nullptr, ev1 = nullptr;
    if (!s2) {
        cudaStreamCreateWithFlags(&s2, cudaStreamNonBlocking);
        cudaEventCreateWithFlags(&ev0, cudaEventDisableTiming);
        cudaEventCreateWithFlags(&evD, cudaEventDisableTiming);
        cudaEventCreateWithFlags(&ev1, cudaEventDisableTiming);
    }

    // fork: weight prep runs on s2 from the start
    cudaEventRecord(ev0, 0);
    cudaStreamWaitEvent(s2, ev0, 0);

    k_count<<<(EE / 4 + 255) / 256, 256>>>(dst);                // #1 main
    k_wprep<<<48, 256, 0, s2>>>(W1, W2);                        // #2 s2
    k_scanA<<<nb_scan, 512>>>();                                // #3 main (scan+dinv)
    cudaEventRecord(evD, 0);                                    // dinv ready

    // s2: tc1 (reads dinv in epilogue -> needs evD), then deg reset
    cudaStreamWaitEvent(s2, evD, 0);
    k_tc<1><<<(NN + 127) / 128, 256, 0, s2>>>(x, nullptr);      // #4 s2 (profiled)
    k_reset<<<(NN + 255) / 256, 256, 0, s2>>>();                // s2
    cudaEventRecord(ev1, s2);

    k_scan3<<<nb_scan, 512>>>();                                // main (fused scan2+3)
    k_fill<<<(EE / 4 + 255) / 256, 256>>>(src, dst);            // main

    // join: agg1 needs CSR (main, in-order) + hs1 (s2)
    cudaStreamWaitEvent(0, ev1, 0);

    k_agg1<<<(NN * 32 + 255) / 256, 256>>>();
    k_tc<2><<<(NN + 127) / 128, 256>>>(nullptr, b1);
    k_agg2<<<(NN * 32 + 255) / 256, 256>>>(b2);
    // 200k warps (2 edges each) = 6.4M threads = 25000 blocks
    k_decode<<<(EPP * 32 + 255) / 256, 256>>>(pos, neg, out);
}